// round 2
// baseline (speedup 1.0000x reference)
#include <cuda_runtime.h>

#define N_NODES_C 100000
#define MEM_C 256
#define B_C 20000
#define DIV_C 8

// Scratch (device globals: allocation-free per harness rules)
__device__ float g_IC[DIV_C * (long long)B_C * 512];  // precomputed i_C for all 8 steps
__device__ float g_ID[(long long)B_C * 512];          // precomputed i_D for final step
__device__ float g_NEW[(long long)B_C * MEM_C];       // staging for scatter
__device__ int   g_IDS[DIV_C * B_C];                  // normalized int32 node ids

// ---------------------------------------------------------------------------
// Normalize node_ids to int32 regardless of whether the input buffer holds
// int32 or int64. Ids are unique within a batch (permutation slice), so for
// int32 data words raw[1], raw[3] are two DISTINCT ids -> cannot both be 0.
// For int64 data (ids < 2^31) both high words are exactly 0.
// ---------------------------------------------------------------------------
__global__ void normalize_ids(const unsigned int* __restrict__ raw,
                              int* __restrict__ out, int n)
{
    const bool is64 = (raw[1] == 0u) && (raw[3] == 0u);
    int t = blockIdx.x * blockDim.x + threadIdx.x;
    if (t < n) out[t] = is64 ? (int)raw[2 * t] : (int)raw[t];
}

// ---------------------------------------------------------------------------
// Generic NT GEMM with optional row gather:
//   C[m][n] = sum_k A[row(m)][k] * W[n][k] + bias[n],  K=256, N=512 (ld 512)
// Tile: 64x64, 256 threads, 4x4 micro-tile, KB=16.
// ---------------------------------------------------------------------------
__global__ __launch_bounds__(256, 2)
void gemm_nt(const float* __restrict__ A, const int* __restrict__ ids, int M,
             const float* __restrict__ W, const float* __restrict__ bias,
             float* __restrict__ C)
{
    __shared__ __align__(16) float As[16][64];
    __shared__ __align__(16) float Bs[16][64];

    const int tid  = threadIdx.x;
    const int row0 = blockIdx.y * 64;
    const int col0 = blockIdx.x * 64;
    const int lr = tid >> 2, kq = tid & 3;   // loader: row 0..63, k-quad 0..3
    const int tr = tid >> 4, tc = tid & 15;  // compute: 16x16 thread grid

    int gr = row0 + lr;
    int arow_idx = 0;
    if (gr < M) arow_idx = ids ? ids[gr] : gr;
    const float* arow = A + (long long)arow_idx * MEM_C + kq * 4;
    const float* wrow = W + (long long)(col0 + lr) * MEM_C + kq * 4;

    float acc[4][4];
#pragma unroll
    for (int i = 0; i < 4; ++i)
#pragma unroll
        for (int j = 0; j < 4; ++j) acc[i][j] = 0.0f;

    for (int k0 = 0; k0 < 256; k0 += 16) {
        float4 av = *reinterpret_cast<const float4*>(arow + k0);
        float4 bv = *reinterpret_cast<const float4*>(wrow + k0);
        __syncthreads();
        As[kq*4+0][lr] = av.x; As[kq*4+1][lr] = av.y;
        As[kq*4+2][lr] = av.z; As[kq*4+3][lr] = av.w;
        Bs[kq*4+0][lr] = bv.x; Bs[kq*4+1][lr] = bv.y;
        Bs[kq*4+2][lr] = bv.z; Bs[kq*4+3][lr] = bv.w;
        __syncthreads();
#pragma unroll
        for (int k = 0; k < 16; ++k) {
            float4 a4 = *reinterpret_cast<const float4*>(&As[k][tr*4]);
            float4 b4 = *reinterpret_cast<const float4*>(&Bs[k][tc*4]);
            float a[4] = {a4.x, a4.y, a4.z, a4.w};
            float b[4] = {b4.x, b4.y, b4.z, b4.w};
#pragma unroll
            for (int i = 0; i < 4; ++i)
#pragma unroll
                for (int j = 0; j < 4; ++j)
                    acc[i][j] = fmaf(a[i], b[j], acc[i][j]);
        }
    }

    float4 bb4 = *reinterpret_cast<const float4*>(bias + col0 + tc*4);
    float bb[4] = {bb4.x, bb4.y, bb4.z, bb4.w};
#pragma unroll
    for (int i = 0; i < 4; ++i) {
        int gm = row0 + tr*4 + i;
        if (gm < M) {
            float4 o;
            o.x = acc[i][0] + bb[0];
            o.y = acc[i][1] + bb[1];
            o.z = acc[i][2] + bb[2];
            o.w = acc[i][3] + bb[3];
            *reinterpret_cast<float4*>(C + (long long)gm * 512 + col0 + tc*4) = o;
        }
    }
}

// ---------------------------------------------------------------------------
// Fused recurrent step: gather mem[ids], compute NS slices of h = m_g @ Wh.T,
// apply gates, write staged new rows to g_NEW. NS=2: slices {1,3} (regular
// step). NS=4: all slices (final step, also consumes i_D).
// ---------------------------------------------------------------------------
template<int NS>
__global__ __launch_bounds__(256, 2)
void step_fused(const float* __restrict__ mem,
                const int* __restrict__ ids,
                const float* __restrict__ Wh, const float* __restrict__ Whb,
                const float* __restrict__ IC, const float* __restrict__ ID,
                float* __restrict__ NEWV)
{
    __shared__ __align__(16) float As[16][64];
    __shared__ __align__(16) float Bs[NS][16][64];
    __shared__ int srow[64];

    const int tid   = threadIdx.x;
    const int row0  = blockIdx.y * 64;
    const int colg0 = blockIdx.x * 64;      // gate-column tile base (0..192)
    const int lr = tid >> 2, kq = tid & 3;
    const int tr = tid >> 4, tc = tid & 15;

    if (tid < 64) {
        int gr = row0 + tid;
        srow[tid] = (gr < B_C) ? ids[gr] : 0;
    }
    __syncthreads();

    const float* arow = mem + (long long)srow[lr] * MEM_C + kq * 4;
    const float* wrow[NS];
#pragma unroll
    for (int s = 0; s < NS; ++s) {
        int soff = (NS == 4) ? s * 256 : 256 + s * 512;  // {0,256,512,768} or {256,768}
        wrow[s] = Wh + (long long)(soff + colg0 + lr) * MEM_C + kq * 4;
    }

    float acc[NS][4][4];
#pragma unroll
    for (int s = 0; s < NS; ++s)
#pragma unroll
        for (int i = 0; i < 4; ++i)
#pragma unroll
            for (int j = 0; j < 4; ++j) acc[s][i][j] = 0.0f;

    for (int k0 = 0; k0 < 256; k0 += 16) {
        float4 av = *reinterpret_cast<const float4*>(arow + k0);
        float4 bv[NS];
#pragma unroll
        for (int s = 0; s < NS; ++s)
            bv[s] = *reinterpret_cast<const float4*>(wrow[s] + k0);
        __syncthreads();
        As[kq*4+0][lr] = av.x; As[kq*4+1][lr] = av.y;
        As[kq*4+2][lr] = av.z; As[kq*4+3][lr] = av.w;
#pragma unroll
        for (int s = 0; s < NS; ++s) {
            Bs[s][kq*4+0][lr] = bv[s].x; Bs[s][kq*4+1][lr] = bv[s].y;
            Bs[s][kq*4+2][lr] = bv[s].z; Bs[s][kq*4+3][lr] = bv[s].w;
        }
        __syncthreads();
#pragma unroll
        for (int k = 0; k < 16; ++k) {
            float4 a4 = *reinterpret_cast<const float4*>(&As[k][tr*4]);
            float a[4] = {a4.x, a4.y, a4.z, a4.w};
#pragma unroll
            for (int s = 0; s < NS; ++s) {
                float4 b4 = *reinterpret_cast<const float4*>(&Bs[s][k][tc*4]);
                float b[4] = {b4.x, b4.y, b4.z, b4.w};
#pragma unroll
                for (int i = 0; i < 4; ++i)
#pragma unroll
                    for (int j = 0; j < 4; ++j)
                        acc[s][i][j] = fmaf(a[i], b[j], acc[s][i][j]);
            }
        }
    }

    // Epilogue: gates + staged write
    const int cb = colg0 + tc * 4;
    float hb[NS][4];
#pragma unroll
    for (int s = 0; s < NS; ++s) {
        int soff = (NS == 4) ? s * 256 : 256 + s * 512;
        float4 b4 = *reinterpret_cast<const float4*>(Whb + soff + cb);
        hb[s][0] = b4.x; hb[s][1] = b4.y; hb[s][2] = b4.z; hb[s][3] = b4.w;
    }

#pragma unroll
    for (int i = 0; i < 4; ++i) {
        int gb = row0 + tr*4 + i;
        if (gb >= B_C) continue;
        int nid = srow[tr*4 + i];
        const float* icr = IC + (long long)gb * 512;

        float4 mg4  = *reinterpret_cast<const float4*>(mem + (long long)nid * MEM_C + cb);
        float4 icg4 = *reinterpret_cast<const float4*>(icr + cb);
        float4 ich4 = *reinterpret_cast<const float4*>(icr + 256 + cb);
        float mg[4]  = {mg4.x, mg4.y, mg4.z, mg4.w};
        float icg[4] = {icg4.x, icg4.y, icg4.z, icg4.w};
        float ich[4] = {ich4.x, ich4.y, ich4.z, ich4.w};

        float o[4];
        if (NS == 2) {
#pragma unroll
            for (int j = 0; j < 4; ++j) {
                float hg = acc[0][i][j] + hb[0][j];
                float hh = acc[1][i][j] + hb[1][j];
                float g  = 1.0f / (1.0f + __expf(-(icg[j] + hg)));
                float hc = tanhf(ich[j] + hh);
                o[j] = (1.0f - g) * hc + g * mg[j];
            }
        } else {
            const float* idr = ID + (long long)gb * 512;
            float4 idg4 = *reinterpret_cast<const float4*>(idr + cb);
            float4 idh4 = *reinterpret_cast<const float4*>(idr + 256 + cb);
            float idg[4] = {idg4.x, idg4.y, idg4.z, idg4.w};
            float idh[4] = {idh4.x, idh4.y, idh4.z, idh4.w};
#pragma unroll
            for (int j = 0; j < 4; ++j) {
                float h0 = acc[0][i][j] + hb[0][j];
                float h1 = acc[1][i][j] + hb[1][j];
                float h2 = acc[2][i][j] + hb[2][j];
                float h3 = acc[3][i][j] + hb[3][j];
                float GD = 1.0f / (1.0f + __expf(-(idg[j] + h0)));
                float GC = 1.0f / (1.0f + __expf(-(icg[j] + h1)));
                float hD = tanhf(idh[j] + h2);
                float hC = tanhf(ich[j] + h3);
                o[j] = 0.5f * (GD * hD + GC * hC + (2.0f - GD - GC) * mg[j]);
            }
        }
        float4 ov = {o[0], o[1], o[2], o[3]};
        *reinterpret_cast<float4*>(NEWV + (long long)gb * MEM_C + cb) = ov;
    }
}

// Scatter staged rows into memory (ids unique within a batch -> no races)
__global__ void scatter_new(float* __restrict__ mem, const int* __restrict__ ids,
                            const float* __restrict__ NEWV)
{
    int t = blockIdx.x * blockDim.x + threadIdx.x;
    if (t >= B_C * 64) return;
    int b = t >> 6, c = t & 63;
    long long r = ids[b];
    reinterpret_cast<float4*>(mem + r * MEM_C)[c] =
        reinterpret_cast<const float4*>(NEWV + (long long)b * MEM_C)[c];
}

extern "C" void kernel_launch(void* const* d_in, const int* in_sizes, int n_in,
                              void* d_out, int out_size)
{
    const float* memory   = (const float*)d_in[0];
    const void*  node_raw = d_in[1];
    const float* messages = (const float*)d_in[2];
    const float* dtdg     = (const float*)d_in[3];
    const float* WCw      = (const float*)d_in[4];
    const float* WCb      = (const float*)d_in[5];
    const float* WDw      = (const float*)d_in[6];
    const float* WDb      = (const float*)d_in[7];
    const float* Whw      = (const float*)d_in[8];
    const float* Whb      = (const float*)d_in[9];
    float* mem = (float*)d_out;

    float *IC, *IDb, *NEWV; int *IDS;
    cudaGetSymbolAddress((void**)&IC,   g_IC);
    cudaGetSymbolAddress((void**)&IDb,  g_ID);
    cudaGetSymbolAddress((void**)&NEWV, g_NEW);
    cudaGetSymbolAddress((void**)&IDS,  g_IDS);

    // Working memory lives in d_out
    cudaMemcpyAsync(mem, memory, (size_t)N_NODES_C * MEM_C * sizeof(float),
                    cudaMemcpyDeviceToDevice);

    // Normalize node ids (int32 vs int64 detection on device)
    normalize_ids<<<(DIV_C * B_C + 255) / 256, 256>>>(
        (const unsigned int*)node_raw, IDS, DIV_C * B_C);

    // Precompute i_C for all 8 steps (no sequential dependency)
    gemm_nt<<<dim3(8, (DIV_C * B_C + 63) / 64), 256>>>(
        messages, nullptr, DIV_C * B_C, WCw, WCb, IC);

    // Precompute i_D for the final step (gathered from dtdg_output)
    gemm_nt<<<dim3(8, (B_C + 63) / 64), 256>>>(
        dtdg, IDS + (DIV_C - 1) * B_C, B_C, WDw, WDb, IDb);

    dim3 sgrid(4, (B_C + 63) / 64);
    const int scb = (B_C * 64 + 255) / 256;

    for (int s = 0; s < DIV_C - 1; ++s) {
        const int* ids_s = IDS + s * B_C;
        step_fused<2><<<sgrid, 256>>>(mem, ids_s, Whw, Whb,
                                      IC + (long long)s * B_C * 512, nullptr, NEWV);
        scatter_new<<<scb, 256>>>(mem, ids_s, NEWV);
    }
    {
        const int* ids_f = IDS + (DIV_C - 1) * B_C;
        step_fused<4><<<sgrid, 256>>>(mem, ids_f, Whw, Whb,
                                      IC + (long long)(DIV_C - 1) * B_C * 512, IDb, NEWV);
        scatter_new<<<scb, 256>>>(mem, ids_f, NEWV);
    }
}

// round 3
// speedup vs baseline: 1.0647x; 1.0647x over previous
#include <cuda_runtime.h>

#define N_NODES_C 100000
#define MEM_C 256
#define B_C 20000
#define DIV_C 8

typedef unsigned long long u64;

// Packed f32x2 helpers (Blackwell sm_103a)
__device__ __forceinline__ u64 pk2(float x, float y) {
    u64 r; asm("mov.b64 %0,{%1,%2};" : "=l"(r) : "f"(x), "f"(y)); return r;
}
__device__ __forceinline__ void fma2(u64& d, u64 a, u64 b) {
    asm("fma.rn.f32x2 %0,%1,%2,%0;" : "+l"(d) : "l"(a), "l"(b));
}
__device__ __forceinline__ float2 up2(u64 v) {
    float lo, hi; asm("mov.b64 {%0,%1},%2;" : "=f"(lo), "=f"(hi) : "l"(v));
    float2 f; f.x = lo; f.y = hi; return f;
}

// Scratch (device globals: allocation-free per harness rules)
__device__ float g_IC[DIV_C * (long long)B_C * 512];
__device__ float g_ID[(long long)B_C * 512];
__device__ float g_NEW[(long long)B_C * MEM_C];
__device__ int   g_IDS[DIV_C * B_C];

// ---------------------------------------------------------------------------
// Normalize node_ids to int32 (handles int32 or int64 input buffer).
// ---------------------------------------------------------------------------
__global__ void normalize_ids(const unsigned int* __restrict__ raw,
                              int* __restrict__ out, int n)
{
    const bool is64 = (raw[1] == 0u) && (raw[3] == 0u);
    int t = blockIdx.x * blockDim.x + threadIdx.x;
    if (t < n) out[t] = is64 ? (int)raw[2 * t] : (int)raw[t];
}

// ---------------------------------------------------------------------------
// Big NT GEMM (optional row gather): C[m] = A[row(m)] @ W^T + bias
// K=256, N=512 (ld 512). Tile 128x128, 256 threads, 8x8 micro-tile, f32x2.
// ---------------------------------------------------------------------------
__global__ __launch_bounds__(256, 2)
void gemmA(const float* __restrict__ A, const int* __restrict__ ids, int M,
           const float* __restrict__ W, const float* __restrict__ bias,
           float* __restrict__ C)
{
    __shared__ __align__(16) float As[16][132];
    __shared__ __align__(16) float Bs[16][132];

    const int tid  = threadIdx.x;
    const int row0 = blockIdx.y * 128;
    const int col0 = blockIdx.x * 128;
    const int lrow = tid & 127;          // loader lane: 32 consecutive rows/warp
    const int lk   = (tid >> 7) * 8;     // k-octet 0 or 8
    const int tr   = tid >> 4, tc = tid & 15;

    int gr = row0 + lrow;
    int aidx = 0;
    if (gr < M) aidx = ids ? ids[gr] : gr;
    const float* arow = A + (long long)aidx * MEM_C + lk;
    const float* wrow = W + (long long)(col0 + lrow) * MEM_C + lk;

    u64 acc[8][4];
#pragma unroll
    for (int i = 0; i < 8; ++i)
#pragma unroll
        for (int j = 0; j < 4; ++j) acc[i][j] = 0ull;

    for (int k0 = 0; k0 < 256; k0 += 16) {
        float4 a0 = *(const float4*)(arow + k0);
        float4 a1 = *(const float4*)(arow + k0 + 4);
        float4 b0 = *(const float4*)(wrow + k0);
        float4 b1 = *(const float4*)(wrow + k0 + 4);
        __syncthreads();
        As[lk+0][lrow] = a0.x; As[lk+1][lrow] = a0.y;
        As[lk+2][lrow] = a0.z; As[lk+3][lrow] = a0.w;
        As[lk+4][lrow] = a1.x; As[lk+5][lrow] = a1.y;
        As[lk+6][lrow] = a1.z; As[lk+7][lrow] = a1.w;
        Bs[lk+0][lrow] = b0.x; Bs[lk+1][lrow] = b0.y;
        Bs[lk+2][lrow] = b0.z; Bs[lk+3][lrow] = b0.w;
        Bs[lk+4][lrow] = b1.x; Bs[lk+5][lrow] = b1.y;
        Bs[lk+6][lrow] = b1.z; Bs[lk+7][lrow] = b1.w;
        __syncthreads();
#pragma unroll
        for (int k = 0; k < 16; ++k) {
            float4 x0 = *(const float4*)(&As[k][tr*8]);
            float4 x1 = *(const float4*)(&As[k][tr*8+4]);
            ulonglong2 y0 = *(const ulonglong2*)(&Bs[k][tc*8]);
            ulonglong2 y1 = *(const ulonglong2*)(&Bs[k][tc*8+4]);
            u64 pb[4] = {y0.x, y0.y, y1.x, y1.y};
            u64 pa[8] = {pk2(x0.x,x0.x), pk2(x0.y,x0.y), pk2(x0.z,x0.z), pk2(x0.w,x0.w),
                         pk2(x1.x,x1.x), pk2(x1.y,x1.y), pk2(x1.z,x1.z), pk2(x1.w,x1.w)};
#pragma unroll
            for (int i = 0; i < 8; ++i)
#pragma unroll
                for (int j = 0; j < 4; ++j)
                    fma2(acc[i][j], pa[i], pb[j]);
        }
    }

    float4 bb0 = *(const float4*)(bias + col0 + tc*8);
    float4 bb1 = *(const float4*)(bias + col0 + tc*8 + 4);
#pragma unroll
    for (int i = 0; i < 8; ++i) {
        int gm = row0 + tr*8 + i;
        if (gm < M) {
            float2 c0 = up2(acc[i][0]), c1 = up2(acc[i][1]);
            float2 c2 = up2(acc[i][2]), c3 = up2(acc[i][3]);
            float4 o0 = {c0.x + bb0.x, c0.y + bb0.y, c1.x + bb0.z, c1.y + bb0.w};
            float4 o1 = {c2.x + bb1.x, c2.y + bb1.y, c3.x + bb1.z, c3.y + bb1.w};
            float* cp = C + (long long)gm * 512 + col0 + tc*8;
            *(float4*)cp       = o0;
            *(float4*)(cp + 4) = o1;
        }
    }
}

// ---------------------------------------------------------------------------
// Fused regular step (slices {1,3} of Wh): gather mem[ids], h-GEMM, gates,
// staged write. Tile 128 rows x 64 gate-cols, 8 rows x 4 cols x 2 slices/thread.
// ---------------------------------------------------------------------------
__global__ __launch_bounds__(256, 2)
void step2(const float* __restrict__ mem, const int* __restrict__ ids,
           const float* __restrict__ Wh, const float* __restrict__ Whb,
           const float* __restrict__ IC, float* __restrict__ NEWV)
{
    __shared__ __align__(16) float As[16][132];
    __shared__ __align__(16) float Bs[2][16][68];
    __shared__ int srow[128];

    const int tid   = threadIdx.x;
    const int row0  = blockIdx.y * 128;
    const int colg0 = blockIdx.x * 64;
    const int lrow  = tid & 127, lk = (tid >> 7) * 8;
    const int bcol  = tid & 63,  bk = (tid >> 6) * 4;
    const int tr    = tid >> 4,  tc = tid & 15;

    if (tid < 128) {
        int gr = row0 + tid;
        srow[tid] = (gr < B_C) ? ids[gr] : 0;
    }
    __syncthreads();

    const float* arow = mem + (long long)srow[lrow] * MEM_C + lk;
    const float* w0 = Wh + (long long)(256 + colg0 + bcol) * MEM_C + bk;  // gate slice
    const float* w1 = Wh + (long long)(768 + colg0 + bcol) * MEM_C + bk;  // tanh slice

    u64 acc[2][8][2];
#pragma unroll
    for (int s = 0; s < 2; ++s)
#pragma unroll
        for (int i = 0; i < 8; ++i) { acc[s][i][0] = 0ull; acc[s][i][1] = 0ull; }

    for (int k0 = 0; k0 < 256; k0 += 16) {
        float4 a0 = *(const float4*)(arow + k0);
        float4 a1 = *(const float4*)(arow + k0 + 4);
        float4 b0 = *(const float4*)(w0 + k0);
        float4 b1 = *(const float4*)(w1 + k0);
        __syncthreads();
        As[lk+0][lrow] = a0.x; As[lk+1][lrow] = a0.y;
        As[lk+2][lrow] = a0.z; As[lk+3][lrow] = a0.w;
        As[lk+4][lrow] = a1.x; As[lk+5][lrow] = a1.y;
        As[lk+6][lrow] = a1.z; As[lk+7][lrow] = a1.w;
        Bs[0][bk+0][bcol] = b0.x; Bs[0][bk+1][bcol] = b0.y;
        Bs[0][bk+2][bcol] = b0.z; Bs[0][bk+3][bcol] = b0.w;
        Bs[1][bk+0][bcol] = b1.x; Bs[1][bk+1][bcol] = b1.y;
        Bs[1][bk+2][bcol] = b1.z; Bs[1][bk+3][bcol] = b1.w;
        __syncthreads();
#pragma unroll
        for (int k = 0; k < 16; ++k) {
            float4 x0 = *(const float4*)(&As[k][tr*8]);
            float4 x1 = *(const float4*)(&As[k][tr*8+4]);
            ulonglong2 yg = *(const ulonglong2*)(&Bs[0][k][tc*4]);
            ulonglong2 yh = *(const ulonglong2*)(&Bs[1][k][tc*4]);
            u64 pa[8] = {pk2(x0.x,x0.x), pk2(x0.y,x0.y), pk2(x0.z,x0.z), pk2(x0.w,x0.w),
                         pk2(x1.x,x1.x), pk2(x1.y,x1.y), pk2(x1.z,x1.z), pk2(x1.w,x1.w)};
#pragma unroll
            for (int i = 0; i < 8; ++i) {
                fma2(acc[0][i][0], pa[i], yg.x);
                fma2(acc[0][i][1], pa[i], yg.y);
                fma2(acc[1][i][0], pa[i], yh.x);
                fma2(acc[1][i][1], pa[i], yh.y);
            }
        }
    }

    const int cb = colg0 + tc * 4;
    float4 hbg = *(const float4*)(Whb + 256 + cb);
    float4 hbh = *(const float4*)(Whb + 768 + cb);
    float hbgv[4] = {hbg.x, hbg.y, hbg.z, hbg.w};
    float hbhv[4] = {hbh.x, hbh.y, hbh.z, hbh.w};

#pragma unroll
    for (int i = 0; i < 8; ++i) {
        int gb = row0 + tr*8 + i;
        if (gb >= B_C) continue;
        int nid = srow[tr*8 + i];
        const float* icr = IC + (long long)gb * 512;
        float4 mg4  = *(const float4*)(mem + (long long)nid * MEM_C + cb);
        float4 icg4 = *(const float4*)(icr + cb);
        float4 ich4 = *(const float4*)(icr + 256 + cb);
        float mg[4]  = {mg4.x, mg4.y, mg4.z, mg4.w};
        float icg[4] = {icg4.x, icg4.y, icg4.z, icg4.w};
        float ich[4] = {ich4.x, ich4.y, ich4.z, ich4.w};
        float2 g0 = up2(acc[0][i][0]), g1 = up2(acc[0][i][1]);
        float2 t0 = up2(acc[1][i][0]), t1 = up2(acc[1][i][1]);
        float hg[4] = {g0.x, g0.y, g1.x, g1.y};
        float ht[4] = {t0.x, t0.y, t1.x, t1.y};
        float o[4];
#pragma unroll
        for (int j = 0; j < 4; ++j) {
            float g  = 1.0f / (1.0f + __expf(-(icg[j] + hg[j] + hbgv[j])));
            float hc = tanhf(ich[j] + ht[j] + hbhv[j]);
            o[j] = (1.0f - g) * hc + g * mg[j];
        }
        float4 ov = {o[0], o[1], o[2], o[3]};
        *(float4*)(NEWV + (long long)gb * MEM_C + cb) = ov;
    }
}

// ---------------------------------------------------------------------------
// Fused final step (all 4 slices, consumes i_C and i_D).
// Tile 64 rows x 64 gate-cols, 4 rows x 4 cols x 4 slices/thread.
// ---------------------------------------------------------------------------
__global__ __launch_bounds__(256, 2)
void step4(const float* __restrict__ mem, const int* __restrict__ ids,
           const float* __restrict__ Wh, const float* __restrict__ Whb,
           const float* __restrict__ IC, const float* __restrict__ ID,
           float* __restrict__ NEWV)
{
    __shared__ __align__(16) float As[16][68];
    __shared__ __align__(16) float Bs[4][16][68];
    __shared__ int srow[64];

    const int tid   = threadIdx.x;
    const int row0  = blockIdx.y * 64;
    const int colg0 = blockIdx.x * 64;
    const int lrow  = tid & 63, lk = (tid >> 6) * 4;
    const int tr    = tid >> 4, tc = tid & 15;

    if (tid < 64) {
        int gr = row0 + tid;
        srow[tid] = (gr < B_C) ? ids[gr] : 0;
    }
    __syncthreads();

    const float* arow = mem + (long long)srow[lrow] * MEM_C + lk;
    const float* ws[4];
#pragma unroll
    for (int s = 0; s < 4; ++s)
        ws[s] = Wh + (long long)(s * 256 + colg0 + lrow) * MEM_C + lk;

    u64 acc[4][4][2];
#pragma unroll
    for (int s = 0; s < 4; ++s)
#pragma unroll
        for (int i = 0; i < 4; ++i) { acc[s][i][0] = 0ull; acc[s][i][1] = 0ull; }

    for (int k0 = 0; k0 < 256; k0 += 16) {
        float4 av = *(const float4*)(arow + k0);
        float4 bv[4];
#pragma unroll
        for (int s = 0; s < 4; ++s) bv[s] = *(const float4*)(ws[s] + k0);
        __syncthreads();
        As[lk+0][lrow] = av.x; As[lk+1][lrow] = av.y;
        As[lk+2][lrow] = av.z; As[lk+3][lrow] = av.w;
#pragma unroll
        for (int s = 0; s < 4; ++s) {
            Bs[s][lk+0][lrow] = bv[s].x; Bs[s][lk+1][lrow] = bv[s].y;
            Bs[s][lk+2][lrow] = bv[s].z; Bs[s][lk+3][lrow] = bv[s].w;
        }
        __syncthreads();
#pragma unroll
        for (int k = 0; k < 16; ++k) {
            float4 x0 = *(const float4*)(&As[k][tr*4]);
            u64 pa[4] = {pk2(x0.x,x0.x), pk2(x0.y,x0.y), pk2(x0.z,x0.z), pk2(x0.w,x0.w)};
#pragma unroll
            for (int s = 0; s < 4; ++s) {
                ulonglong2 y = *(const ulonglong2*)(&Bs[s][k][tc*4]);
#pragma unroll
                for (int i = 0; i < 4; ++i) {
                    fma2(acc[s][i][0], pa[i], y.x);
                    fma2(acc[s][i][1], pa[i], y.y);
                }
            }
        }
    }

    const int cb = colg0 + tc * 4;
    float hbv[4][4];
#pragma unroll
    for (int s = 0; s < 4; ++s) {
        float4 b4 = *(const float4*)(Whb + s * 256 + cb);
        hbv[s][0] = b4.x; hbv[s][1] = b4.y; hbv[s][2] = b4.z; hbv[s][3] = b4.w;
    }

#pragma unroll
    for (int i = 0; i < 4; ++i) {
        int gb = row0 + tr*4 + i;
        if (gb >= B_C) continue;
        int nid = srow[tr*4 + i];
        const float* icr = IC + (long long)gb * 512;
        const float* idr = ID + (long long)gb * 512;
        float4 mg4  = *(const float4*)(mem + (long long)nid * MEM_C + cb);
        float4 icg4 = *(const float4*)(icr + cb);
        float4 ich4 = *(const float4*)(icr + 256 + cb);
        float4 idg4 = *(const float4*)(idr + cb);
        float4 idh4 = *(const float4*)(idr + 256 + cb);
        float mg[4]  = {mg4.x, mg4.y, mg4.z, mg4.w};
        float icg[4] = {icg4.x, icg4.y, icg4.z, icg4.w};
        float ich[4] = {ich4.x, ich4.y, ich4.z, ich4.w};
        float idg[4] = {idg4.x, idg4.y, idg4.z, idg4.w};
        float idh[4] = {idh4.x, idh4.y, idh4.z, idh4.w};
        float h[4][4];
#pragma unroll
        for (int s = 0; s < 4; ++s) {
            float2 p0 = up2(acc[s][i][0]), p1 = up2(acc[s][i][1]);
            h[s][0] = p0.x + hbv[s][0]; h[s][1] = p0.y + hbv[s][1];
            h[s][2] = p1.x + hbv[s][2]; h[s][3] = p1.y + hbv[s][3];
        }
        float o[4];
#pragma unroll
        for (int j = 0; j < 4; ++j) {
            float GD = 1.0f / (1.0f + __expf(-(idg[j] + h[0][j])));
            float GC = 1.0f / (1.0f + __expf(-(icg[j] + h[1][j])));
            float hD = tanhf(idh[j] + h[2][j]);
            float hC = tanhf(ich[j] + h[3][j]);
            o[j] = 0.5f * (GD * hD + GC * hC + (2.0f - GD - GC) * mg[j]);
        }
        float4 ov = {o[0], o[1], o[2], o[3]};
        *(float4*)(NEWV + (long long)gb * MEM_C + cb) = ov;
    }
}

// Scatter staged rows into memory (ids unique within a batch -> no races)
__global__ void scatter_new(float* __restrict__ mem, const int* __restrict__ ids,
                            const float* __restrict__ NEWV)
{
    int t = blockIdx.x * blockDim.x + threadIdx.x;
    if (t >= B_C * 64) return;
    int b = t >> 6, c = t & 63;
    long long r = ids[b];
    reinterpret_cast<float4*>(mem + r * MEM_C)[c] =
        reinterpret_cast<const float4*>(NEWV + (long long)b * MEM_C)[c];
}

extern "C" void kernel_launch(void* const* d_in, const int* in_sizes, int n_in,
                              void* d_out, int out_size)
{
    const float* memory   = (const float*)d_in[0];
    const void*  node_raw = d_in[1];
    const float* messages = (const float*)d_in[2];
    const float* dtdg     = (const float*)d_in[3];
    const float* WCw      = (const float*)d_in[4];
    const float* WCb      = (const float*)d_in[5];
    const float* WDw      = (const float*)d_in[6];
    const float* WDb      = (const float*)d_in[7];
    const float* Whw      = (const float*)d_in[8];
    const float* Whb      = (const float*)d_in[9];
    float* mem = (float*)d_out;

    float *IC, *IDb, *NEWV; int *IDS;
    cudaGetSymbolAddress((void**)&IC,   g_IC);
    cudaGetSymbolAddress((void**)&IDb,  g_ID);
    cudaGetSymbolAddress((void**)&NEWV, g_NEW);
    cudaGetSymbolAddress((void**)&IDS,  g_IDS);

    cudaMemcpyAsync(mem, memory, (size_t)N_NODES_C * MEM_C * sizeof(float),
                    cudaMemcpyDeviceToDevice);

    normalize_ids<<<(DIV_C * B_C + 255) / 256, 256>>>(
        (const unsigned int*)node_raw, IDS, DIV_C * B_C);

    // Precompute i_C for all 8 steps (no sequential dependency)
    gemmA<<<dim3(4, (DIV_C * B_C + 127) / 128), 256>>>(
        messages, nullptr, DIV_C * B_C, WCw, WCb, IC);

    // Precompute i_D for the final step (gathered from dtdg_output)
    gemmA<<<dim3(4, (B_C + 127) / 128), 256>>>(
        dtdg, IDS + (DIV_C - 1) * B_C, B_C, WDw, WDb, IDb);

    const int scb = (B_C * 64 + 255) / 256;
    dim3 s2grid(4, (B_C + 127) / 128);
    dim3 s4grid(4, (B_C + 63) / 64);

    for (int s = 0; s < DIV_C - 1; ++s) {
        const int* ids_s = IDS + s * B_C;
        step2<<<s2grid, 256>>>(mem, ids_s, Whw, Whb,
                               IC + (long long)s * B_C * 512, NEWV);
        scatter_new<<<scb, 256>>>(mem, ids_s, NEWV);
    }
    {
        const int* ids_f = IDS + (DIV_C - 1) * B_C;
        step4<<<s4grid, 256>>>(mem, ids_f, Whw, Whb,
                               IC + (long long)(DIV_C - 1) * B_C * 512, IDb, NEWV);
        scatter_new<<<scb, 256>>>(mem, ids_f, NEWV);
    }
}

// round 4
// speedup vs baseline: 1.0880x; 1.0219x over previous
#include <cuda_runtime.h>

#define N_NODES_C 100000
#define MEM_C 256
#define B_C 20000
#define DIV_C 8

typedef unsigned long long u64;

// Packed f32x2 helpers (Blackwell sm_103a)
__device__ __forceinline__ u64 pk2(float x, float y) {
    u64 r; asm("mov.b64 %0,{%1,%2};" : "=l"(r) : "f"(x), "f"(y)); return r;
}
__device__ __forceinline__ void fma2(u64& d, u64 a, u64 b) {
    asm("fma.rn.f32x2 %0,%1,%2,%0;" : "+l"(d) : "l"(a), "l"(b));
}
__device__ __forceinline__ float2 up2(u64 v) {
    float lo, hi; asm("mov.b64 {%0,%1},%2;" : "=f"(lo), "=f"(hi) : "l"(v));
    float2 f; f.x = lo; f.y = hi; return f;
}

// Scratch (device globals: allocation-free per harness rules)
__device__ float g_IC[DIV_C * (long long)B_C * 512];
__device__ float g_ID[(long long)B_C * 512];
__device__ float g_NEW[(long long)B_C * MEM_C];
__device__ int   g_IDS[DIV_C * B_C];

// ---------------------------------------------------------------------------
// Normalize node_ids to int32 (handles int32 or int64 input buffer).
// ---------------------------------------------------------------------------
__global__ void normalize_ids(const unsigned int* __restrict__ raw,
                              int* __restrict__ out, int n)
{
    const bool is64 = (raw[1] == 0u) && (raw[3] == 0u);
    int t = blockIdx.x * blockDim.x + threadIdx.x;
    if (t < n) out[t] = is64 ? (int)raw[2 * t] : (int)raw[t];
}

// ---------------------------------------------------------------------------
// Big NT GEMM (optional row gather): C[m] = A[row(m)] @ W^T + bias
// K=256, N=512 (ld 512). Tile 128x128, 256 threads, 8x8 micro-tile, f32x2.
// Software-pipelined: next tile's LDG issued before the FMA block.
// ---------------------------------------------------------------------------
__global__ __launch_bounds__(256, 2)
void gemmA(const float* __restrict__ A, const int* __restrict__ ids, int M,
           const float* __restrict__ W, const float* __restrict__ bias,
           float* __restrict__ C)
{
    __shared__ __align__(16) float As[16][132];
    __shared__ __align__(16) float Bs[16][132];

    const int tid  = threadIdx.x;
    const int row0 = blockIdx.y * 128;
    const int col0 = blockIdx.x * 128;
    const int lrow = tid & 127;
    const int lk   = (tid >> 7) * 8;
    const int tr   = tid >> 4, tc = tid & 15;

    int gr = row0 + lrow;
    int aidx = 0;
    if (gr < M) aidx = ids ? ids[gr] : gr;
    const float* arow = A + (long long)aidx * MEM_C + lk;
    const float* wrow = W + (long long)(col0 + lrow) * MEM_C + lk;

    u64 acc[8][4];
#pragma unroll
    for (int i = 0; i < 8; ++i)
#pragma unroll
        for (int j = 0; j < 4; ++j) acc[i][j] = 0ull;

    float4 a0 = *(const float4*)(arow);
    float4 a1 = *(const float4*)(arow + 4);
    float4 b0 = *(const float4*)(wrow);
    float4 b1 = *(const float4*)(wrow + 4);

#pragma unroll 1
    for (int k0 = 0; k0 < 256; k0 += 16) {
        __syncthreads();
        As[lk+0][lrow] = a0.x; As[lk+1][lrow] = a0.y;
        As[lk+2][lrow] = a0.z; As[lk+3][lrow] = a0.w;
        As[lk+4][lrow] = a1.x; As[lk+5][lrow] = a1.y;
        As[lk+6][lrow] = a1.z; As[lk+7][lrow] = a1.w;
        Bs[lk+0][lrow] = b0.x; Bs[lk+1][lrow] = b0.y;
        Bs[lk+2][lrow] = b0.z; Bs[lk+3][lrow] = b0.w;
        Bs[lk+4][lrow] = b1.x; Bs[lk+5][lrow] = b1.y;
        Bs[lk+6][lrow] = b1.z; Bs[lk+7][lrow] = b1.w;
        __syncthreads();
        // Prefetch next tile (wraps to 0 on last iter; values discarded)
        int kn = (k0 + 16) & 255;
        a0 = *(const float4*)(arow + kn);
        a1 = *(const float4*)(arow + kn + 4);
        b0 = *(const float4*)(wrow + kn);
        b1 = *(const float4*)(wrow + kn + 4);
#pragma unroll
        for (int k = 0; k < 16; ++k) {
            float4 x0 = *(const float4*)(&As[k][tr*8]);
            float4 x1 = *(const float4*)(&As[k][tr*8+4]);
            ulonglong2 y0 = *(const ulonglong2*)(&Bs[k][tc*8]);
            ulonglong2 y1 = *(const ulonglong2*)(&Bs[k][tc*8+4]);
            u64 pb[4] = {y0.x, y0.y, y1.x, y1.y};
            u64 pa[8] = {pk2(x0.x,x0.x), pk2(x0.y,x0.y), pk2(x0.z,x0.z), pk2(x0.w,x0.w),
                         pk2(x1.x,x1.x), pk2(x1.y,x1.y), pk2(x1.z,x1.z), pk2(x1.w,x1.w)};
#pragma unroll
            for (int i = 0; i < 8; ++i)
#pragma unroll
                for (int j = 0; j < 4; ++j)
                    fma2(acc[i][j], pa[i], pb[j]);
        }
    }

    float4 bb0 = *(const float4*)(bias + col0 + tc*8);
    float4 bb1 = *(const float4*)(bias + col0 + tc*8 + 4);
#pragma unroll
    for (int i = 0; i < 8; ++i) {
        int gm = row0 + tr*8 + i;
        if (gm < M) {
            float2 c0 = up2(acc[i][0]), c1 = up2(acc[i][1]);
            float2 c2 = up2(acc[i][2]), c3 = up2(acc[i][3]);
            float4 o0 = {c0.x + bb0.x, c0.y + bb0.y, c1.x + bb0.z, c1.y + bb0.w};
            float4 o1 = {c2.x + bb1.x, c2.y + bb1.y, c3.x + bb1.z, c3.y + bb1.w};
            float* cp = C + (long long)gm * 512 + col0 + tc*8;
            *(float4*)cp       = o0;
            *(float4*)(cp + 4) = o1;
        }
    }
}

// ---------------------------------------------------------------------------
// Fused regular step (slices {1,3} of Wh), software-pipelined.
// Tile 128 rows x 64 gate-cols, 8 rows x 4 cols x 2 slices/thread.
// ---------------------------------------------------------------------------
__global__ __launch_bounds__(256, 2)
void step2(const float* __restrict__ mem, const int* __restrict__ ids,
           const float* __restrict__ Wh, const float* __restrict__ Whb,
           const float* __restrict__ IC, float* __restrict__ NEWV)
{
    __shared__ __align__(16) float As[16][132];
    __shared__ __align__(16) float Bs[2][16][68];
    __shared__ int srow[128];

    const int tid   = threadIdx.x;
    const int row0  = blockIdx.y * 128;
    const int colg0 = blockIdx.x * 64;
    const int lrow  = tid & 127, lk = (tid >> 7) * 8;
    const int bcol  = tid & 63,  bk = (tid >> 6) * 4;
    const int tr    = tid >> 4,  tc = tid & 15;

    if (tid < 128) {
        int gr = row0 + tid;
        srow[tid] = (gr < B_C) ? ids[gr] : 0;
    }
    __syncthreads();

    const float* arow = mem + (long long)srow[lrow] * MEM_C + lk;
    const float* w0 = Wh + (long long)(256 + colg0 + bcol) * MEM_C + bk;
    const float* w1 = Wh + (long long)(768 + colg0 + bcol) * MEM_C + bk;

    u64 acc[2][8][2];
#pragma unroll
    for (int s = 0; s < 2; ++s)
#pragma unroll
        for (int i = 0; i < 8; ++i) { acc[s][i][0] = 0ull; acc[s][i][1] = 0ull; }

    float4 a0 = *(const float4*)(arow);
    float4 a1 = *(const float4*)(arow + 4);
    float4 b0 = *(const float4*)(w0);
    float4 b1 = *(const float4*)(w1);

#pragma unroll 1
    for (int k0 = 0; k0 < 256; k0 += 16) {
        __syncthreads();
        As[lk+0][lrow] = a0.x; As[lk+1][lrow] = a0.y;
        As[lk+2][lrow] = a0.z; As[lk+3][lrow] = a0.w;
        As[lk+4][lrow] = a1.x; As[lk+5][lrow] = a1.y;
        As[lk+6][lrow] = a1.z; As[lk+7][lrow] = a1.w;
        Bs[0][bk+0][bcol] = b0.x; Bs[0][bk+1][bcol] = b0.y;
        Bs[0][bk+2][bcol] = b0.z; Bs[0][bk+3][bcol] = b0.w;
        Bs[1][bk+0][bcol] = b1.x; Bs[1][bk+1][bcol] = b1.y;
        Bs[1][bk+2][bcol] = b1.z; Bs[1][bk+3][bcol] = b1.w;
        __syncthreads();
        int kn = (k0 + 16) & 255;
        a0 = *(const float4*)(arow + kn);
        a1 = *(const float4*)(arow + kn + 4);
        b0 = *(const float4*)(w0 + kn);
        b1 = *(const float4*)(w1 + kn);
#pragma unroll
        for (int k = 0; k < 16; ++k) {
            float4 x0 = *(const float4*)(&As[k][tr*8]);
            float4 x1 = *(const float4*)(&As[k][tr*8+4]);
            ulonglong2 yg = *(const ulonglong2*)(&Bs[0][k][tc*4]);
            ulonglong2 yh = *(const ulonglong2*)(&Bs[1][k][tc*4]);
            u64 pa[8] = {pk2(x0.x,x0.x), pk2(x0.y,x0.y), pk2(x0.z,x0.z), pk2(x0.w,x0.w),
                         pk2(x1.x,x1.x), pk2(x1.y,x1.y), pk2(x1.z,x1.z), pk2(x1.w,x1.w)};
#pragma unroll
            for (int i = 0; i < 8; ++i) {
                fma2(acc[0][i][0], pa[i], yg.x);
                fma2(acc[0][i][1], pa[i], yg.y);
                fma2(acc[1][i][0], pa[i], yh.x);
                fma2(acc[1][i][1], pa[i], yh.y);
            }
        }
    }

    const int cb = colg0 + tc * 4;
    float4 hbg = *(const float4*)(Whb + 256 + cb);
    float4 hbh = *(const float4*)(Whb + 768 + cb);
    float hbgv[4] = {hbg.x, hbg.y, hbg.z, hbg.w};
    float hbhv[4] = {hbh.x, hbh.y, hbh.z, hbh.w};

#pragma unroll
    for (int i = 0; i < 8; ++i) {
        int gb = row0 + tr*8 + i;
        if (gb >= B_C) continue;
        int nid = srow[tr*8 + i];
        const float* icr = IC + (long long)gb * 512;
        float4 mg4  = *(const float4*)(mem + (long long)nid * MEM_C + cb);
        float4 icg4 = *(const float4*)(icr + cb);
        float4 ich4 = *(const float4*)(icr + 256 + cb);
        float mg[4]  = {mg4.x, mg4.y, mg4.z, mg4.w};
        float icg[4] = {icg4.x, icg4.y, icg4.z, icg4.w};
        float ich[4] = {ich4.x, ich4.y, ich4.z, ich4.w};
        float2 g0 = up2(acc[0][i][0]), g1 = up2(acc[0][i][1]);
        float2 t0 = up2(acc[1][i][0]), t1 = up2(acc[1][i][1]);
        float hg[4] = {g0.x, g0.y, g1.x, g1.y};
        float ht[4] = {t0.x, t0.y, t1.x, t1.y};
        float o[4];
#pragma unroll
        for (int j = 0; j < 4; ++j) {
            float g  = 1.0f / (1.0f + __expf(-(icg[j] + hg[j] + hbgv[j])));
            float hc = tanhf(ich[j] + ht[j] + hbhv[j]);
            o[j] = (1.0f - g) * hc + g * mg[j];
        }
        float4 ov = {o[0], o[1], o[2], o[3]};
        *(float4*)(NEWV + (long long)gb * MEM_C + cb) = ov;
    }
}

// ---------------------------------------------------------------------------
// Fused final step (all 4 slices, consumes i_C and i_D), pipelined.
// Tile 64 rows x 64 gate-cols, 4 rows x 4 cols x 4 slices/thread.
// ---------------------------------------------------------------------------
__global__ __launch_bounds__(256, 2)
void step4(const float* __restrict__ mem, const int* __restrict__ ids,
           const float* __restrict__ Wh, const float* __restrict__ Whb,
           const float* __restrict__ IC, const float* __restrict__ ID,
           float* __restrict__ NEWV)
{
    __shared__ __align__(16) float As[16][68];
    __shared__ __align__(16) float Bs[4][16][68];
    __shared__ int srow[64];

    const int tid   = threadIdx.x;
    const int row0  = blockIdx.y * 64;
    const int colg0 = blockIdx.x * 64;
    const int lrow  = tid & 63, lk = (tid >> 6) * 4;
    const int tr    = tid >> 4, tc = tid & 15;

    if (tid < 64) {
        int gr = row0 + tid;
        srow[tid] = (gr < B_C) ? ids[gr] : 0;
    }
    __syncthreads();

    const float* arow = mem + (long long)srow[lrow] * MEM_C + lk;
    const float* ws[4];
#pragma unroll
    for (int s = 0; s < 4; ++s)
        ws[s] = Wh + (long long)(s * 256 + colg0 + lrow) * MEM_C + lk;

    u64 acc[4][4][2];
#pragma unroll
    for (int s = 0; s < 4; ++s)
#pragma unroll
        for (int i = 0; i < 4; ++i) { acc[s][i][0] = 0ull; acc[s][i][1] = 0ull; }

    float4 av = *(const float4*)(arow);
    float4 bv[4];
#pragma unroll
    for (int s = 0; s < 4; ++s) bv[s] = *(const float4*)(ws[s]);

#pragma unroll 1
    for (int k0 = 0; k0 < 256; k0 += 16) {
        __syncthreads();
        As[lk+0][lrow] = av.x; As[lk+1][lrow] = av.y;
        As[lk+2][lrow] = av.z; As[lk+3][lrow] = av.w;
#pragma unroll
        for (int s = 0; s < 4; ++s) {
            Bs[s][lk+0][lrow] = bv[s].x; Bs[s][lk+1][lrow] = bv[s].y;
            Bs[s][lk+2][lrow] = bv[s].z; Bs[s][lk+3][lrow] = bv[s].w;
        }
        __syncthreads();
        int kn = (k0 + 16) & 255;
        av = *(const float4*)(arow + kn);
#pragma unroll
        for (int s = 0; s < 4; ++s) bv[s] = *(const float4*)(ws[s] + kn);
#pragma unroll
        for (int k = 0; k < 16; ++k) {
            float4 x0 = *(const float4*)(&As[k][tr*4]);
            u64 pa[4] = {pk2(x0.x,x0.x), pk2(x0.y,x0.y), pk2(x0.z,x0.z), pk2(x0.w,x0.w)};
#pragma unroll
            for (int s = 0; s < 4; ++s) {
                ulonglong2 y = *(const ulonglong2*)(&Bs[s][k][tc*4]);
#pragma unroll
                for (int i = 0; i < 4; ++i) {
                    fma2(acc[s][i][0], pa[i], y.x);
                    fma2(acc[s][i][1], pa[i], y.y);
                }
            }
        }
    }

    const int cb = colg0 + tc * 4;
    float hbv[4][4];
#pragma unroll
    for (int s = 0; s < 4; ++s) {
        float4 b4 = *(const float4*)(Whb + s * 256 + cb);
        hbv[s][0] = b4.x; hbv[s][1] = b4.y; hbv[s][2] = b4.z; hbv[s][3] = b4.w;
    }

#pragma unroll
    for (int i = 0; i < 4; ++i) {
        int gb = row0 + tr*4 + i;
        if (gb >= B_C) continue;
        int nid = srow[tr*4 + i];
        const float* icr = IC + (long long)gb * 512;
        const float* idr = ID + (long long)gb * 512;
        float4 mg4  = *(const float4*)(mem + (long long)nid * MEM_C + cb);
        float4 icg4 = *(const float4*)(icr + cb);
        float4 ich4 = *(const float4*)(icr + 256 + cb);
        float4 idg4 = *(const float4*)(idr + cb);
        float4 idh4 = *(const float4*)(idr + 256 + cb);
        float mg[4]  = {mg4.x, mg4.y, mg4.z, mg4.w};
        float icg[4] = {icg4.x, icg4.y, icg4.z, icg4.w};
        float ich[4] = {ich4.x, ich4.y, ich4.z, ich4.w};
        float idg[4] = {idg4.x, idg4.y, idg4.z, idg4.w};
        float idh[4] = {idh4.x, idh4.y, idh4.z, idh4.w};
        float h[4][4];
#pragma unroll
        for (int s = 0; s < 4; ++s) {
            float2 p0 = up2(acc[s][i][0]), p1 = up2(acc[s][i][1]);
            h[s][0] = p0.x + hbv[s][0]; h[s][1] = p0.y + hbv[s][1];
            h[s][2] = p1.x + hbv[s][2]; h[s][3] = p1.y + hbv[s][3];
        }
        float o[4];
#pragma unroll
        for (int j = 0; j < 4; ++j) {
            float GD = 1.0f / (1.0f + __expf(-(idg[j] + h[0][j])));
            float GC = 1.0f / (1.0f + __expf(-(icg[j] + h[1][j])));
            float hD = tanhf(idh[j] + h[2][j]);
            float hC = tanhf(ich[j] + h[3][j]);
            o[j] = 0.5f * (GD * hD + GC * hC + (2.0f - GD - GC) * mg[j]);
        }
        float4 ov = {o[0], o[1], o[2], o[3]};
        *(float4*)(NEWV + (long long)gb * MEM_C + cb) = ov;
    }
}

// Scatter staged rows into memory (ids unique within a batch -> no races)
__global__ void scatter_new(float* __restrict__ mem, const int* __restrict__ ids,
                            const float* __restrict__ NEWV)
{
    int t = blockIdx.x * blockDim.x + threadIdx.x;
    if (t >= B_C * 64) return;
    int b = t >> 6, c = t & 63;
    long long r = ids[b];
    reinterpret_cast<float4*>(mem + r * MEM_C)[c] =
        reinterpret_cast<const float4*>(NEWV + (long long)b * MEM_C)[c];
}

extern "C" void kernel_launch(void* const* d_in, const int* in_sizes, int n_in,
                              void* d_out, int out_size)
{
    const float* memory   = (const float*)d_in[0];
    const void*  node_raw = d_in[1];
    const float* messages = (const float*)d_in[2];
    const float* dtdg     = (const float*)d_in[3];
    const float* WCw      = (const float*)d_in[4];
    const float* WCb      = (const float*)d_in[5];
    const float* WDw      = (const float*)d_in[6];
    const float* WDb      = (const float*)d_in[7];
    const float* Whw      = (const float*)d_in[8];
    const float* Whb      = (const float*)d_in[9];
    float* mem = (float*)d_out;

    float *IC, *IDb, *NEWV; int *IDS;
    cudaGetSymbolAddress((void**)&IC,   g_IC);
    cudaGetSymbolAddress((void**)&IDb,  g_ID);
    cudaGetSymbolAddress((void**)&NEWV, g_NEW);
    cudaGetSymbolAddress((void**)&IDS,  g_IDS);

    cudaMemcpyAsync(mem, memory, (size_t)N_NODES_C * MEM_C * sizeof(float),
                    cudaMemcpyDeviceToDevice);

    normalize_ids<<<(DIV_C * B_C + 255) / 256, 256>>>(
        (const unsigned int*)node_raw, IDS, DIV_C * B_C);

    // Precompute i_C for all 8 steps (no sequential dependency)
    gemmA<<<dim3(4, (DIV_C * B_C + 127) / 128), 256>>>(
        messages, nullptr, DIV_C * B_C, WCw, WCb, IC);

    // Precompute i_D for the final step (gathered from dtdg_output)
    gemmA<<<dim3(4, (B_C + 127) / 128), 256>>>(
        dtdg, IDS + (DIV_C - 1) * B_C, B_C, WDw, WDb, IDb);

    const int scb = (B_C * 64 + 255) / 256;
    dim3 s2grid(4, (B_C + 127) / 128);
    dim3 s4grid(4, (B_C + 63) / 64);

    for (int s = 0; s < DIV_C - 1; ++s) {
        const int* ids_s = IDS + s * B_C;
        step2<<<s2grid, 256>>>(mem, ids_s, Whw, Whb,
                               IC + (long long)s * B_C * 512, NEWV);
        scatter_new<<<scb, 256>>>(mem, ids_s, NEWV);
    }
    {
        const int* ids_f = IDS + (DIV_C - 1) * B_C;
        step4<<<s4grid, 256>>>(mem, ids_f, Whw, Whb,
                               IC + (long long)(DIV_C - 1) * B_C * 512, IDb, NEWV);
        scatter_new<<<scb, 256>>>(mem, ids_f, NEWV);
    }
}

// round 6
// speedup vs baseline: 1.6621x; 1.5276x over previous
#include <cuda_runtime.h>
#include <cuda_bf16.h>
#include <cstdint>

#define MEM_C 256
#define B_C 20000
#define DIV_C 8
#define N_NODES_C 100000

// Stage layout (bytes): bf16 tiles, 80B row stride (64B data + 16 pad)
#define ST_A_HI 0
#define ST_A_LO 10240
#define ST_B_HI 20480
#define ST_B_LO 30720
#define ST_SIZE 40960
#define SM_SROW 81920
#define SM_TOTAL (81920 + 640)

// Scratch (device globals: allocation-free per harness rules)
__device__ float g_IC[DIV_C * (long long)B_C * 512];
__device__ float g_ID[(long long)B_C * 512];
__device__ int   g_IDS[DIV_C * B_C];

__device__ __forceinline__ uint32_t smem_u32(const void* p) {
    uint32_t a;
    asm("{ .reg .u64 t; cvta.to.shared.u64 t, %1; cvt.u32.u64 %0, t; }" : "=r"(a) : "l"(p));
    return a;
}

#define LDM4(r0, r1, r2, r3, addr)                                          \
    asm volatile("ldmatrix.sync.aligned.m8n8.x4.shared.b16 {%0,%1,%2,%3}, [%4];" \
                 : "=r"(r0), "=r"(r1), "=r"(r2), "=r"(r3) : "r"(addr))

#define MMA_BF16(c, a, b)                                                   \
    asm volatile("mma.sync.aligned.m16n8k16.row.col.f32.bf16.bf16.f32 "     \
                 "{%0,%1,%2,%3},{%4,%5,%6,%7},{%8,%9},{%0,%1,%2,%3};"       \
                 : "+f"((c)[0]), "+f"((c)[1]), "+f"((c)[2]), "+f"((c)[3])   \
                 : "r"((a)[0]), "r"((a)[1]), "r"((a)[2]), "r"((a)[3]),      \
                   "r"((b)[0]), "r"((b)[1]))

__global__ void normalize_ids(const unsigned int* __restrict__ raw,
                              int* __restrict__ out, int n)
{
    const bool is64 = (raw[1] == 0u) && (raw[3] == 0u);
    int t = blockIdx.x * blockDim.x + threadIdx.x;
    if (t < n) out[t] = is64 ? (int)raw[2 * t] : (int)raw[t];
}

// Convert 16 fp32 -> bf16 hi/lo, store as 2x uint4 each.
__device__ __forceinline__ void cvt_sts(char* hi, char* lo, const float4* v)
{
    uint32_t h[8], l[8];
    const float* f = (const float*)v;
#pragma unroll
    for (int i = 0; i < 8; ++i) {
        float x = f[2*i], y = f[2*i+1];
        __nv_bfloat162 hb = __floats2bfloat162_rn(x, y);
        float xr = x - __bfloat162float(__low2bfloat16(hb));
        float yr = y - __bfloat162float(__high2bfloat16(hb));
        __nv_bfloat162 lb = __floats2bfloat162_rn(xr, yr);
        h[i] = *(uint32_t*)&hb; l[i] = *(uint32_t*)&lb;
    }
    ((uint4*)hi)[0] = make_uint4(h[0], h[1], h[2], h[3]);
    ((uint4*)hi)[1] = make_uint4(h[4], h[5], h[6], h[7]);
    ((uint4*)lo)[0] = make_uint4(l[0], l[1], l[2], l[3]);
    ((uint4*)lo)[1] = make_uint4(l[4], l[5], l[6], l[7]);
}

// ---------------------------------------------------------------------------
// Unified mma.sync bf16-split GEMM engine.
// CTA tile: 128 gathered rows x 128 W-rows (4 quarters of 32 via roff).
// MODE 0: C[gb][roff[q]+jj] = D + bias           (IC / ID precompute)
// MODE 1: regular step (slices 1,3), in-place mem[ids] update
// MODE 2: final step fully fused (all 4 slices), in-place update
// ---------------------------------------------------------------------------
template<int MODE>
__global__ __launch_bounds__(256)
void mma_gemm(const float* __restrict__ A, const int* __restrict__ ids, int M,
              const float* __restrict__ W, const float* __restrict__ bias,
              const float* __restrict__ X, const float* __restrict__ Y,
              float* __restrict__ C, float* __restrict__ memv)
{
    extern __shared__ __align__(16) char smem[];
    const int tid = threadIdx.x, lane = tid & 31, wid = tid >> 5;
    const int g = blockIdx.x, row0 = blockIdx.y * 128;

    int r0q, r1q, r2q, r3q;
    if (MODE == 0)      { r0q = 64*g;     r1q = r0q + 32; r2q = 256 + 64*g; r3q = r2q + 32; }
    else if (MODE == 1) { r0q = 256+64*g; r1q = r0q + 32; r2q = 768 + 64*g; r3q = r2q + 32; }
    else                { r0q = 32*g;     r1q = 256+32*g; r2q = 512 + 32*g; r3q = 768 + 32*g; }

    int* srow = (int*)(smem + SM_SROW);
    if (tid < 128) {
        int gr = row0 + tid;
        if (gr >= M) gr = M - 1;
        srow[tid] = ids ? ids[gr] : gr;
    }
    __syncthreads();

    // Loader mapping: thread -> (row ra, 16-col half)
    const int ra = tid >> 1, half = (tid & 1) * 16;
    const float* ap = A + (long long)srow[ra] * MEM_C + half;
    const int q = ra >> 5;
    const int wr = (q == 0 ? r0q : q == 1 ? r1q : q == 2 ? r2q : r3q) + (ra & 31);
    const float* bp = W + (long long)wr * MEM_C + half;
    char* sAh = smem + ST_A_HI + ra * 80 + (tid & 1) * 32;
    char* sAl = smem + ST_A_LO + ra * 80 + (tid & 1) * 32;
    char* sBh = smem + ST_B_HI + ra * 80 + (tid & 1) * 32;
    char* sBl = smem + ST_B_LO + ra * 80 + (tid & 1) * 32;

    // ldmatrix lane bases
    const int wm = wid >> 2, wn = wid & 3;
    const uint32_t sb = smem_u32(smem);
    const uint32_t aoff = sb + ST_A_HI +
        (64*wm + (lane & 7) + 8*((lane >> 3) & 1)) * 80 + (lane >> 4) * 16;
    const uint32_t boff0 = sb + ST_B_HI +
        (32*wn + (lane & 7) + (lane >> 4) * 8) * 80 + ((lane >> 3) & 1) * 16;
    const uint32_t boff1 = boff0 + 16 * 80;

    float acc[4][4][4];
#pragma unroll
    for (int i = 0; i < 4; ++i)
#pragma unroll
        for (int j = 0; j < 4; ++j)
#pragma unroll
            for (int e = 0; e < 4; ++e) acc[i][j][e] = 0.0f;

    float4 fa[4], fb[4];
#pragma unroll
    for (int i = 0; i < 4; ++i) {
        fa[i] = *(const float4*)(ap + i * 4);
        fb[i] = *(const float4*)(bp + i * 4);
    }
    cvt_sts(sAh, sAl, fa);
    cvt_sts(sBh, sBl, fb);
    __syncthreads();

#pragma unroll 1
    for (int kc = 0; kc < 8; ++kc) {
        const uint32_t so = (uint32_t)(kc & 1) * ST_SIZE;
        if (kc < 7) {
            int kb = (kc + 1) * 32;
#pragma unroll
            for (int i = 0; i < 4; ++i) {
                fa[i] = *(const float4*)(ap + kb + i * 4);
                fb[i] = *(const float4*)(bp + kb + i * 4);
            }
        }
#pragma unroll
        for (int kk = 0; kk < 2; ++kk) {
            uint32_t ka  = aoff  + so + kk * 32;
            uint32_t kb0 = boff0 + so + kk * 32;
            uint32_t kb1 = boff1 + so + kk * 32;
            uint32_t ah[4][4], al[4][4], bh[4][2], bl[4][2];
#pragma unroll
            for (int tm = 0; tm < 4; ++tm) {
                LDM4(ah[tm][0], ah[tm][1], ah[tm][2], ah[tm][3], ka + tm * 1280);
                LDM4(al[tm][0], al[tm][1], al[tm][2], al[tm][3], ka + tm * 1280 + 10240);
            }
            LDM4(bh[0][0], bh[0][1], bh[1][0], bh[1][1], kb0);
            LDM4(bh[2][0], bh[2][1], bh[3][0], bh[3][1], kb1);
            LDM4(bl[0][0], bl[0][1], bl[1][0], bl[1][1], kb0 + 10240);
            LDM4(bl[2][0], bl[2][1], bl[3][0], bl[3][1], kb1 + 10240);
#pragma unroll
            for (int tm = 0; tm < 4; ++tm)
#pragma unroll
                for (int tn = 0; tn < 4; ++tn) {
                    MMA_BF16(acc[tm][tn], ah[tm], bh[tn]);
                    MMA_BF16(acc[tm][tn], ah[tm], bl[tn]);
                    MMA_BF16(acc[tm][tn], al[tm], bh[tn]);
                }
        }
        if (kc < 7) {
            uint32_t o = (uint32_t)((kc + 1) & 1) * ST_SIZE;
            cvt_sts(sAh + o, sAl + o, fa);
            cvt_sts(sBh + o, sBl + o, fb);
        }
        __syncthreads();
    }

    // Stage D through smem (reuse stage buffers), 132-float row stride
    float* Cs = (float*)smem;
#pragma unroll
    for (int tm = 0; tm < 4; ++tm)
#pragma unroll
        for (int tn = 0; tn < 4; ++tn) {
            int rr = 64*wm + 16*tm + (lane >> 2);
            int cc = 32*wn + 8*tn + 2*(lane & 3);
            Cs[rr * 132 + cc]       = acc[tm][tn][0];
            Cs[rr * 132 + cc + 1]   = acc[tm][tn][1];
            Cs[(rr+8) * 132 + cc]     = acc[tm][tn][2];
            Cs[(rr+8) * 132 + cc + 1] = acc[tm][tn][3];
        }
    __syncthreads();

    const int r = tid >> 1, seg = tid & 1;
    const int gb = row0 + r;
    if (gb < M) {
        if (MODE == 0) {
#pragma unroll
            for (int qq = 0; qq < 2; ++qq) {
                int qi = 2*seg + qq;
                int ob = (qi == 0 ? r0q : qi == 1 ? r1q : qi == 2 ? r2q : r3q);
#pragma unroll
                for (int jj = 0; jj < 32; jj += 4) {
                    float4 v  = *(float4*)&Cs[r * 132 + qi * 32 + jj];
                    float4 bv = *(const float4*)(bias + ob + jj);
                    v.x += bv.x; v.y += bv.y; v.z += bv.z; v.w += bv.w;
                    *(float4*)(C + (long long)gb * 512 + ob + jj) = v;
                }
            }
        } else if (MODE == 1) {
            int nid = srow[r];
            int c0 = r0q - 256;  // 64g
#pragma unroll
            for (int jj = 32*seg; jj < 32*seg + 32; jj += 4) {
                float4 hg4 = *(float4*)&Cs[r * 132 + jj];
                float4 ht4 = *(float4*)&Cs[r * 132 + 64 + jj];
                float4 bg = *(const float4*)(bias + r0q + jj);
                float4 bt = *(const float4*)(bias + r2q + jj);
                float4 xg = *(const float4*)(X + (long long)gb * 512 + c0 + jj);
                float4 xt = *(const float4*)(X + (long long)gb * 512 + r0q + jj);
                float4 mg = *(const float4*)(memv + (long long)nid * 256 + c0 + jj);
                float o[4];
                const float* HG = (const float*)&hg4; const float* HT = (const float*)&ht4;
                const float* BG = (const float*)&bg;  const float* BT = (const float*)&bt;
                const float* XG = (const float*)&xg;  const float* XT = (const float*)&xt;
                const float* MG = (const float*)&mg;
#pragma unroll
                for (int e = 0; e < 4; ++e) {
                    float gg = 1.0f / (1.0f + __expf(-(XG[e] + HG[e] + BG[e])));
                    float tt = tanhf(XT[e] + HT[e] + BT[e]);
                    o[e] = (1.0f - gg) * tt + gg * MG[e];
                }
                *(float4*)(memv + (long long)nid * 256 + c0 + jj) =
                    make_float4(o[0], o[1], o[2], o[3]);
            }
        } else {
            int nid = srow[r];
            int c0 = r0q;  // 32g
#pragma unroll
            for (int jj = 16*seg; jj < 16*seg + 16; jj += 4) {
                float4 hgd = *(float4*)&Cs[r * 132 + jj];
                float4 hgc = *(float4*)&Cs[r * 132 + 32 + jj];
                float4 hhd = *(float4*)&Cs[r * 132 + 64 + jj];
                float4 hhc = *(float4*)&Cs[r * 132 + 96 + jj];
                float4 b0 = *(const float4*)(bias + r0q + jj);
                float4 b1 = *(const float4*)(bias + r1q + jj);
                float4 b2 = *(const float4*)(bias + r2q + jj);
                float4 b3 = *(const float4*)(bias + r3q + jj);
                float4 icg = *(const float4*)(X + (long long)gb * 512 + r0q + jj);
                float4 ich = *(const float4*)(X + (long long)gb * 512 + r1q + jj);
                float4 idg = *(const float4*)(Y + (long long)gb * 512 + r0q + jj);
                float4 idh = *(const float4*)(Y + (long long)gb * 512 + r1q + jj);
                float4 mg = *(const float4*)(memv + (long long)nid * 256 + c0 + jj);
                float o[4];
                const float* P0 = (const float*)&hgd; const float* P1 = (const float*)&hgc;
                const float* P2 = (const float*)&hhd; const float* P3 = (const float*)&hhc;
                const float* B0 = (const float*)&b0;  const float* B1 = (const float*)&b1;
                const float* B2 = (const float*)&b2;  const float* B3 = (const float*)&b3;
                const float* ICG = (const float*)&icg; const float* ICH = (const float*)&ich;
                const float* IDG = (const float*)&idg; const float* IDH = (const float*)&idh;
                const float* MG = (const float*)&mg;
#pragma unroll
                for (int e = 0; e < 4; ++e) {
                    float GD = 1.0f / (1.0f + __expf(-(IDG[e] + P0[e] + B0[e])));
                    float GC = 1.0f / (1.0f + __expf(-(ICG[e] + P1[e] + B1[e])));
                    float hD = tanhf(IDH[e] + P2[e] + B2[e]);
                    float hC = tanhf(ICH[e] + P3[e] + B3[e]);
                    o[e] = 0.5f * (GD * hD + GC * hC + (2.0f - GD - GC) * MG[e]);
                }
                *(float4*)(memv + (long long)nid * 256 + c0 + jj) =
                    make_float4(o[0], o[1], o[2], o[3]);
            }
        }
    }
}

// ---------------------------------------------------------------------------
extern "C" void kernel_launch(void* const* d_in, const int* in_sizes, int n_in,
                              void* d_out, int out_size)
{
    const float* memory   = (const float*)d_in[0];
    const void*  node_raw = d_in[1];
    const float* messages = (const float*)d_in[2];
    const float* dtdg     = (const float*)d_in[3];
    const float* WCw      = (const float*)d_in[4];
    const float* WCb      = (const float*)d_in[5];
    const float* WDw      = (const float*)d_in[6];
    const float* WDb      = (const float*)d_in[7];
    const float* Whw      = (const float*)d_in[8];
    const float* Whb      = (const float*)d_in[9];
    float* mem = (float*)d_out;

    float *IC, *IDb; int *IDS;
    cudaGetSymbolAddress((void**)&IC,  g_IC);
    cudaGetSymbolAddress((void**)&IDb, g_ID);
    cudaGetSymbolAddress((void**)&IDS, g_IDS);

    cudaFuncSetAttribute(mma_gemm<0>, cudaFuncAttributeMaxDynamicSharedMemorySize, SM_TOTAL);
    cudaFuncSetAttribute(mma_gemm<1>, cudaFuncAttributeMaxDynamicSharedMemorySize, SM_TOTAL);
    cudaFuncSetAttribute(mma_gemm<2>, cudaFuncAttributeMaxDynamicSharedMemorySize, SM_TOTAL);

    cudaMemcpyAsync(mem, memory, (size_t)N_NODES_C * MEM_C * sizeof(float),
                    cudaMemcpyDeviceToDevice);

    normalize_ids<<<(DIV_C * B_C + 255) / 256, 256>>>(
        (const unsigned int*)node_raw, IDS, DIV_C * B_C);

    const int* ids7 = IDS + (DIV_C - 1) * B_C;
    const int gy = (B_C + 127) / 128;  // 157

    // i_C for all 8 steps
    mma_gemm<0><<<dim3(4, (DIV_C * B_C) / 128), 256, SM_TOTAL>>>(
        messages, nullptr, DIV_C * B_C, WCw, WCb, nullptr, nullptr, IC, nullptr);

    // i_D for the final step (gathered)
    mma_gemm<0><<<dim3(4, gy), 256, SM_TOTAL>>>(
        dtdg, ids7, B_C, WDw, WDb, nullptr, nullptr, IDb, nullptr);

    // 7 regular steps, in-place mem update
    for (int s = 0; s < DIV_C - 1; ++s) {
        mma_gemm<1><<<dim3(4, gy), 256, SM_TOTAL>>>(
            mem, IDS + s * B_C, B_C, Whw, Whb,
            IC + (long long)s * B_C * 512, nullptr, nullptr, mem);
    }
    // Final step, fully fused (all 4 slices)
    mma_gemm<2><<<dim3(8, gy), 256, SM_TOTAL>>>(
        mem, ids7, B_C, Whw, Whb,
        IC + (long long)(DIV_C - 1) * B_C * 512, IDb, nullptr, mem);
}

// round 7
// speedup vs baseline: 1.9506x; 1.1736x over previous
#include <cuda_runtime.h>
#include <cuda_bf16.h>
#include <cstdint>

#define MEM_C 256
#define B_C 20000
#define DIV_C 8
#define N_NODES_C 100000

// Stage layout (bytes): bf16 tiles, 80B row stride (64B data + 16 pad)
#define ST_A_HI 0
#define ST_A_LO 10240
#define ST_B_HI 20480
#define ST_B_LO 30720
#define ST_SIZE 40960
#define SM_SROW 81920
#define SM_TOTAL (81920 + 640)

// Scratch (device globals: allocation-free per harness rules)
__device__ float g_IC[DIV_C * (long long)B_C * 512];
__device__ float g_ID[(long long)B_C * 512];
__device__ int   g_IDS[DIV_C * B_C];

__device__ __forceinline__ uint32_t smem_u32(const void* p) {
    uint32_t a;
    asm("{ .reg .u64 t; cvta.to.shared.u64 t, %1; cvt.u32.u64 %0, t; }" : "=r"(a) : "l"(p));
    return a;
}

#define LDM4(r0, r1, r2, r3, addr)                                          \
    asm volatile("ldmatrix.sync.aligned.m8n8.x4.shared.b16 {%0,%1,%2,%3}, [%4];" \
                 : "=r"(r0), "=r"(r1), "=r"(r2), "=r"(r3) : "r"(addr))

#define MMA_BF16(c, a, b)                                                   \
    asm volatile("mma.sync.aligned.m16n8k16.row.col.f32.bf16.bf16.f32 "     \
                 "{%0,%1,%2,%3},{%4,%5,%6,%7},{%8,%9},{%0,%1,%2,%3};"       \
                 : "+f"((c)[0]), "+f"((c)[1]), "+f"((c)[2]), "+f"((c)[3])   \
                 : "r"((a)[0]), "r"((a)[1]), "r"((a)[2]), "r"((a)[3]),      \
                   "r"((b)[0]), "r"((b)[1]))

__global__ void normalize_ids(const unsigned int* __restrict__ raw,
                              int* __restrict__ out, int n)
{
    const bool is64 = (raw[1] == 0u) && (raw[3] == 0u);
    int t = blockIdx.x * blockDim.x + threadIdx.x;
    if (t < n) out[t] = is64 ? (int)raw[2 * t] : (int)raw[t];
}

// Convert 16 fp32 -> bf16 hi/lo, store as 2x uint4 each.
__device__ __forceinline__ void cvt_sts(char* hi, char* lo, const float4* v)
{
    uint32_t h[8], l[8];
    const float* f = (const float*)v;
#pragma unroll
    for (int i = 0; i < 8; ++i) {
        float x = f[2*i], y = f[2*i+1];
        __nv_bfloat162 hb = __floats2bfloat162_rn(x, y);
        float xr = x - __bfloat162float(__low2bfloat16(hb));
        float yr = y - __bfloat162float(__high2bfloat16(hb));
        __nv_bfloat162 lb = __floats2bfloat162_rn(xr, yr);
        h[i] = *(uint32_t*)&hb; l[i] = *(uint32_t*)&lb;
    }
    ((uint4*)hi)[0] = make_uint4(h[0], h[1], h[2], h[3]);
    ((uint4*)hi)[1] = make_uint4(h[4], h[5], h[6], h[7]);
    ((uint4*)lo)[0] = make_uint4(l[0], l[1], l[2], l[3]);
    ((uint4*)lo)[1] = make_uint4(l[4], l[5], l[6], l[7]);
}

// ---------------------------------------------------------------------------
// Unified mma.sync bf16-split GEMM engine.
// CTA tile: 128 gathered rows x 128 W-rows (4 quarters of 32 via roff).
// MODE 0: C[gb][roff[q]+jj] = D + bias           (IC / ID precompute)
// MODE 1: regular step (slices 1,3), in-place mem[ids] update
// MODE 2: final step fully fused (all 4 slices), in-place update
// ---------------------------------------------------------------------------
template<int MODE>
__global__ __launch_bounds__(256, 2)
void mma_gemm(const float* __restrict__ A, const int* __restrict__ ids, int M,
              const float* __restrict__ W, const float* __restrict__ bias,
              const float* __restrict__ X, const float* __restrict__ Y,
              float* __restrict__ C, float* __restrict__ memv)
{
    extern __shared__ __align__(16) char smem[];
    const int tid = threadIdx.x, lane = tid & 31, wid = tid >> 5;
    const int g = blockIdx.x, row0 = blockIdx.y * 128;

    int r0q, r1q, r2q, r3q;
    if (MODE == 0)      { r0q = 64*g;     r1q = r0q + 32; r2q = 256 + 64*g; r3q = r2q + 32; }
    else if (MODE == 1) { r0q = 256+64*g; r1q = r0q + 32; r2q = 768 + 64*g; r3q = r2q + 32; }
    else                { r0q = 32*g;     r1q = 256+32*g; r2q = 512 + 32*g; r3q = 768 + 32*g; }

    int* srow = (int*)(smem + SM_SROW);
    if (tid < 128) {
        int gr = row0 + tid;
        if (gr >= M) gr = M - 1;
        srow[tid] = ids ? ids[gr] : gr;
    }
    __syncthreads();

    // Loader mapping: thread -> (row ra, 16-col half)
    const int ra = tid >> 1, half = (tid & 1) * 16;
    const float* ap = A + (long long)srow[ra] * MEM_C + half;
    const int q = ra >> 5;
    const int wr = (q == 0 ? r0q : q == 1 ? r1q : q == 2 ? r2q : r3q) + (ra & 31);
    const float* bp = W + (long long)wr * MEM_C + half;
    char* sAh = smem + ST_A_HI + ra * 80 + (tid & 1) * 32;
    char* sAl = smem + ST_A_LO + ra * 80 + (tid & 1) * 32;
    char* sBh = smem + ST_B_HI + ra * 80 + (tid & 1) * 32;
    char* sBl = smem + ST_B_LO + ra * 80 + (tid & 1) * 32;

    // ldmatrix lane bases
    const int wm = wid >> 2, wn = wid & 3;
    const uint32_t sb = smem_u32(smem);
    const uint32_t aoff = sb + ST_A_HI +
        (64*wm + (lane & 7) + 8*((lane >> 3) & 1)) * 80 + (lane >> 4) * 16;
    const uint32_t boff0 = sb + ST_B_HI +
        (32*wn + (lane & 7) + (lane >> 4) * 8) * 80 + ((lane >> 3) & 1) * 16;
    const uint32_t boff1 = boff0 + 16 * 80;

    float acc[4][4][4];
#pragma unroll
    for (int i = 0; i < 4; ++i)
#pragma unroll
        for (int j = 0; j < 4; ++j)
#pragma unroll
            for (int e = 0; e < 4; ++e) acc[i][j][e] = 0.0f;

#pragma unroll 1
    for (int kc = 0; kc < 8; ++kc) {
        const uint32_t so = (uint32_t)(kc & 1) * ST_SIZE;
        // Load + convert + store this chunk (no register prefetch: keeps
        // live regs <=128 so 2 CTAs/SM co-reside and overlap each other)
        {
            const int kb = kc * 32;
            float4 fa[4], fb[4];
#pragma unroll
            for (int i = 0; i < 4; ++i) {
                fa[i] = *(const float4*)(ap + kb + i * 4);
                fb[i] = *(const float4*)(bp + kb + i * 4);
            }
            cvt_sts(sAh + so, sAl + so, fa);
            cvt_sts(sBh + so, sBl + so, fb);
        }
        __syncthreads();
#pragma unroll
        for (int kk = 0; kk < 2; ++kk) {
            uint32_t ka  = aoff  + so + kk * 32;
            uint32_t kb0 = boff0 + so + kk * 32;
            uint32_t kb1 = boff1 + so + kk * 32;
            uint32_t ah[4][4], al[4][4], bh[4][2], bl[4][2];
#pragma unroll
            for (int tm = 0; tm < 4; ++tm) {
                LDM4(ah[tm][0], ah[tm][1], ah[tm][2], ah[tm][3], ka + tm * 1280);
                LDM4(al[tm][0], al[tm][1], al[tm][2], al[tm][3], ka + tm * 1280 + 10240);
            }
            LDM4(bh[0][0], bh[0][1], bh[1][0], bh[1][1], kb0);
            LDM4(bh[2][0], bh[2][1], bh[3][0], bh[3][1], kb1);
            LDM4(bl[0][0], bl[0][1], bl[1][0], bl[1][1], kb0 + 10240);
            LDM4(bl[2][0], bl[2][1], bl[3][0], bl[3][1], kb1 + 10240);
#pragma unroll
            for (int tm = 0; tm < 4; ++tm)
#pragma unroll
                for (int tn = 0; tn < 4; ++tn) {
                    MMA_BF16(acc[tm][tn], ah[tm], bh[tn]);
                    MMA_BF16(acc[tm][tn], ah[tm], bl[tn]);
                    MMA_BF16(acc[tm][tn], al[tm], bh[tn]);
                }
        }
    }
    __syncthreads();   // last MMA reads buf1; Cs staging overwrites it

    // Stage D through smem, 132-float row stride
    float* Cs = (float*)smem;
#pragma unroll
    for (int tm = 0; tm < 4; ++tm)
#pragma unroll
        for (int tn = 0; tn < 4; ++tn) {
            int rr = 64*wm + 16*tm + (lane >> 2);
            int cc = 32*wn + 8*tn + 2*(lane & 3);
            Cs[rr * 132 + cc]       = acc[tm][tn][0];
            Cs[rr * 132 + cc + 1]   = acc[tm][tn][1];
            Cs[(rr+8) * 132 + cc]     = acc[tm][tn][2];
            Cs[(rr+8) * 132 + cc + 1] = acc[tm][tn][3];
        }
    __syncthreads();

    const int r = tid >> 1, seg = tid & 1;
    const int gb = row0 + r;
    if (gb < M) {
        if (MODE == 0) {
#pragma unroll
            for (int qq = 0; qq < 2; ++qq) {
                int qi = 2*seg + qq;
                int ob = (qi == 0 ? r0q : qi == 1 ? r1q : qi == 2 ? r2q : r3q);
#pragma unroll
                for (int jj = 0; jj < 32; jj += 4) {
                    float4 v  = *(float4*)&Cs[r * 132 + qi * 32 + jj];
                    float4 bv = *(const float4*)(bias + ob + jj);
                    v.x += bv.x; v.y += bv.y; v.z += bv.z; v.w += bv.w;
                    *(float4*)(C + (long long)gb * 512 + ob + jj) = v;
                }
            }
        } else if (MODE == 1) {
            int nid = srow[r];
            int c0 = r0q - 256;  // 64g
#pragma unroll
            for (int jj = 32*seg; jj < 32*seg + 32; jj += 4) {
                float4 hg4 = *(float4*)&Cs[r * 132 + jj];
                float4 ht4 = *(float4*)&Cs[r * 132 + 64 + jj];
                float4 bg = *(const float4*)(bias + r0q + jj);
                float4 bt = *(const float4*)(bias + r2q + jj);
                float4 xg = *(const float4*)(X + (long long)gb * 512 + c0 + jj);
                float4 xt = *(const float4*)(X + (long long)gb * 512 + r0q + jj);
                float4 mg = *(const float4*)(memv + (long long)nid * 256 + c0 + jj);
                float o[4];
                const float* HG = (const float*)&hg4; const float* HT = (const float*)&ht4;
                const float* BG = (const float*)&bg;  const float* BT = (const float*)&bt;
                const float* XG = (const float*)&xg;  const float* XT = (const float*)&xt;
                const float* MG = (const float*)&mg;
#pragma unroll
                for (int e = 0; e < 4; ++e) {
                    float gg = 1.0f / (1.0f + __expf(-(XG[e] + HG[e] + BG[e])));
                    float tt = tanhf(XT[e] + HT[e] + BT[e]);
                    o[e] = (1.0f - gg) * tt + gg * MG[e];
                }
                *(float4*)(memv + (long long)nid * 256 + c0 + jj) =
                    make_float4(o[0], o[1], o[2], o[3]);
            }
        } else {
            int nid = srow[r];
            int c0 = r0q;  // 32g
#pragma unroll
            for (int jj = 16*seg; jj < 16*seg + 16; jj += 4) {
                float4 hgd = *(float4*)&Cs[r * 132 + jj];
                float4 hgc = *(float4*)&Cs[r * 132 + 32 + jj];
                float4 hhd = *(float4*)&Cs[r * 132 + 64 + jj];
                float4 hhc = *(float4*)&Cs[r * 132 + 96 + jj];
                float4 b0 = *(const float4*)(bias + r0q + jj);
                float4 b1 = *(const float4*)(bias + r1q + jj);
                float4 b2 = *(const float4*)(bias + r2q + jj);
                float4 b3 = *(const float4*)(bias + r3q + jj);
                float4 icg = *(const float4*)(X + (long long)gb * 512 + r0q + jj);
                float4 ich = *(const float4*)(X + (long long)gb * 512 + r1q + jj);
                float4 idg = *(const float4*)(Y + (long long)gb * 512 + r0q + jj);
                float4 idh = *(const float4*)(Y + (long long)gb * 512 + r1q + jj);
                float4 mg = *(const float4*)(memv + (long long)nid * 256 + c0 + jj);
                float o[4];
                const float* P0 = (const float*)&hgd; const float* P1 = (const float*)&hgc;
                const float* P2 = (const float*)&hhd; const float* P3 = (const float*)&hhc;
                const float* B0 = (const float*)&b0;  const float* B1 = (const float*)&b1;
                const float* B2 = (const float*)&b2;  const float* B3 = (const float*)&b3;
                const float* ICG = (const float*)&icg; const float* ICH = (const float*)&ich;
                const float* IDG = (const float*)&idg; const float* IDH = (const float*)&idh;
                const float* MG = (const float*)&mg;
#pragma unroll
                for (int e = 0; e < 4; ++e) {
                    float GD = 1.0f / (1.0f + __expf(-(IDG[e] + P0[e] + B0[e])));
                    float GC = 1.0f / (1.0f + __expf(-(ICG[e] + P1[e] + B1[e])));
                    float hD = tanhf(IDH[e] + P2[e] + B2[e]);
                    float hC = tanhf(ICH[e] + P3[e] + B3[e]);
                    o[e] = 0.5f * (GD * hD + GC * hC + (2.0f - GD - GC) * MG[e]);
                }
                *(float4*)(memv + (long long)nid * 256 + c0 + jj) =
                    make_float4(o[0], o[1], o[2], o[3]);
            }
        }
    }
}

// ---------------------------------------------------------------------------
extern "C" void kernel_launch(void* const* d_in, const int* in_sizes, int n_in,
                              void* d_out, int out_size)
{
    const float* memory   = (const float*)d_in[0];
    const void*  node_raw = d_in[1];
    const float* messages = (const float*)d_in[2];
    const float* dtdg     = (const float*)d_in[3];
    const float* WCw      = (const float*)d_in[4];
    const float* WCb      = (const float*)d_in[5];
    const float* WDw      = (const float*)d_in[6];
    const float* WDb      = (const float*)d_in[7];
    const float* Whw      = (const float*)d_in[8];
    const float* Whb      = (const float*)d_in[9];
    float* mem = (float*)d_out;

    float *IC, *IDb; int *IDS;
    cudaGetSymbolAddress((void**)&IC,  g_IC);
    cudaGetSymbolAddress((void**)&IDb, g_ID);
    cudaGetSymbolAddress((void**)&IDS, g_IDS);

    cudaFuncSetAttribute(mma_gemm<0>, cudaFuncAttributeMaxDynamicSharedMemorySize, SM_TOTAL);
    cudaFuncSetAttribute(mma_gemm<1>, cudaFuncAttributeMaxDynamicSharedMemorySize, SM_TOTAL);
    cudaFuncSetAttribute(mma_gemm<2>, cudaFuncAttributeMaxDynamicSharedMemorySize, SM_TOTAL);

    cudaMemcpyAsync(mem, memory, (size_t)N_NODES_C * MEM_C * sizeof(float),
                    cudaMemcpyDeviceToDevice);

    normalize_ids<<<(DIV_C * B_C + 255) / 256, 256>>>(
        (const unsigned int*)node_raw, IDS, DIV_C * B_C);

    const int* ids7 = IDS + (DIV_C - 1) * B_C;
    const int gy = (B_C + 127) / 128;  // 157

    // i_C for all 8 steps
    mma_gemm<0><<<dim3(4, (DIV_C * B_C) / 128), 256, SM_TOTAL>>>(
        messages, nullptr, DIV_C * B_C, WCw, WCb, nullptr, nullptr, IC, nullptr);

    // i_D for the final step (gathered)
    mma_gemm<0><<<dim3(4, gy), 256, SM_TOTAL>>>(
        dtdg, ids7, B_C, WDw, WDb, nullptr, nullptr, IDb, nullptr);

    // 7 regular steps, in-place mem update
    for (int s = 0; s < DIV_C - 1; ++s) {
        mma_gemm<1><<<dim3(4, gy), 256, SM_TOTAL>>>(
            mem, IDS + s * B_C, B_C, Whw, Whb,
            IC + (long long)s * B_C * 512, nullptr, nullptr, mem);
    }
    // Final step, fully fused (all 4 slices)
    mma_gemm<2><<<dim3(8, gy), 256, SM_TOTAL>>>(
        mem, ids7, B_C, Whw, Whb,
        IC + (long long)(DIV_C - 1) * B_C * 512, IDb, nullptr, mem);
}

// round 8
// speedup vs baseline: 2.0289x; 1.0401x over previous
#include <cuda_runtime.h>
#include <cuda_bf16.h>
#include <cstdint>

#define MEM_C 256
#define B_C 20000
#define DIV_C 8
#define N_NODES_C 100000

// Stage layout (bytes): bf16 tiles, 80B row stride (64B data + 16 pad)
#define ST_A_HI 0
#define ST_A_LO 10240
#define ST_B_HI 20480
#define ST_B_LO 30720
#define ST_SIZE 40960
#define SM_SROW 81920
#define SM_TOTAL (81920 + 640)

// Scratch (device globals: allocation-free per harness rules)
__device__ float    g_IC[DIV_C * (long long)B_C * 512];
__device__ float    g_ID[(long long)B_C * 512];
__device__ int      g_IDS[DIV_C * B_C];
__device__ uint16_t g_MSGhi[DIV_C * (long long)B_C * MEM_C];
__device__ uint16_t g_MSGlo[DIV_C * (long long)B_C * MEM_C];
__device__ uint16_t g_MEMhi[(long long)N_NODES_C * MEM_C];
__device__ uint16_t g_MEMlo[(long long)N_NODES_C * MEM_C];
__device__ uint16_t g_DThi[(long long)B_C * MEM_C];
__device__ uint16_t g_DTlo[(long long)B_C * MEM_C];
__device__ uint16_t g_WChi[512 * MEM_C], g_WClo[512 * MEM_C];
__device__ uint16_t g_WDhi[512 * MEM_C], g_WDlo[512 * MEM_C];
__device__ uint16_t g_Whhi[1024 * MEM_C], g_Whlo[1024 * MEM_C];

__device__ __forceinline__ uint32_t smem_u32(const void* p) {
    uint32_t a;
    asm("{ .reg .u64 t; cvta.to.shared.u64 t, %1; cvt.u32.u64 %0, t; }" : "=r"(a) : "l"(p));
    return a;
}

#define LDM4(r0, r1, r2, r3, addr)                                          \
    asm volatile("ldmatrix.sync.aligned.m8n8.x4.shared.b16 {%0,%1,%2,%3}, [%4];" \
                 : "=r"(r0), "=r"(r1), "=r"(r2), "=r"(r3) : "r"(addr))

#define MMA_BF16(c, a, b)                                                   \
    asm volatile("mma.sync.aligned.m16n8k16.row.col.f32.bf16.bf16.f32 "     \
                 "{%0,%1,%2,%3},{%4,%5,%6,%7},{%8,%9},{%0,%1,%2,%3};"       \
                 : "+f"((c)[0]), "+f"((c)[1]), "+f"((c)[2]), "+f"((c)[3])   \
                 : "r"((a)[0]), "r"((a)[1]), "r"((a)[2]), "r"((a)[3]),      \
                   "r"((b)[0]), "r"((b)[1]))

#define CP16(dst, src)                                                      \
    asm volatile("cp.async.cg.shared.global [%0], [%1], 16;"                \
                 :: "r"(dst), "l"(src))
#define CP_COMMIT() asm volatile("cp.async.commit_group;" ::: "memory")
#define CP_WAIT1()  asm volatile("cp.async.wait_group 1;" ::: "memory")
#define CP_WAIT0()  asm volatile("cp.async.wait_group 0;" ::: "memory")

__global__ void normalize_ids(const unsigned int* __restrict__ raw,
                              int* __restrict__ out, int n)
{
    const bool is64 = (raw[1] == 0u) && (raw[3] == 0u);
    int t = blockIdx.x * blockDim.x + threadIdx.x;
    if (t < n) out[t] = is64 ? (int)raw[2 * t] : (int)raw[t];
}

// fp32 -> bf16 hi/lo split, vectorized float4 per thread
__device__ __forceinline__ void split4(float4 v, uint2& h, uint2& l)
{
    __nv_bfloat162 h01 = __floats2bfloat162_rn(v.x, v.y);
    __nv_bfloat162 h23 = __floats2bfloat162_rn(v.z, v.w);
    float rx = v.x - __bfloat162float(__low2bfloat16(h01));
    float ry = v.y - __bfloat162float(__high2bfloat16(h01));
    float rz = v.z - __bfloat162float(__low2bfloat16(h23));
    float rw = v.w - __bfloat162float(__high2bfloat16(h23));
    __nv_bfloat162 l01 = __floats2bfloat162_rn(rx, ry);
    __nv_bfloat162 l23 = __floats2bfloat162_rn(rz, rw);
    h = make_uint2(*(uint32_t*)&h01, *(uint32_t*)&h23);
    l = make_uint2(*(uint32_t*)&l01, *(uint32_t*)&l23);
}

__global__ void cvt_split(const float* __restrict__ src, uint16_t* __restrict__ hi,
                          uint16_t* __restrict__ lo, long long n4)
{
    long long t = (long long)blockIdx.x * blockDim.x + threadIdx.x;
    if (t >= n4) return;
    uint2 h, l;
    split4(reinterpret_cast<const float4*>(src)[t], h, l);
    reinterpret_cast<uint2*>(hi)[t] = h;
    reinterpret_cast<uint2*>(lo)[t] = l;
}

// Gather-convert B_C rows (compact output)
__global__ void cvt_gather(const float* __restrict__ src, const int* __restrict__ ids,
                           uint16_t* __restrict__ hi, uint16_t* __restrict__ lo)
{
    int t = blockIdx.x * blockDim.x + threadIdx.x;
    if (t >= B_C * 64) return;
    int b = t >> 6, q = t & 63;
    uint2 h, l;
    split4(*(const float4*)(src + (long long)ids[b] * MEM_C + q * 4), h, l);
    reinterpret_cast<uint2*>(hi)[(long long)b * 64 + q] = h;
    reinterpret_cast<uint2*>(lo)[(long long)b * 64 + q] = l;
}

// ---------------------------------------------------------------------------
// Unified mma.sync bf16-split GEMM engine, cp.async double-buffered.
// Operands are preconverted bf16 hi/lo in global memory.
// MODE 0: C[gb][quarters] = D + bias      (IC / ID precompute)
// MODE 1: regular step (slices 1,3), in-place mem update + hi/lo refresh
// MODE 2: final step fully fused (all 4 slices), in-place update
// ---------------------------------------------------------------------------
template<int MODE>
__global__ __launch_bounds__(256, 2)
void mma_gemm(const uint16_t* __restrict__ Ahi, const uint16_t* __restrict__ Alo,
              const int* __restrict__ ids, int M,
              const uint16_t* __restrict__ Whi, const uint16_t* __restrict__ Wlo,
              const float* __restrict__ bias,
              const float* __restrict__ X, const float* __restrict__ Y,
              float* __restrict__ C, float* __restrict__ memv,
              uint16_t* __restrict__ mhi, uint16_t* __restrict__ mlo)
{
    extern __shared__ __align__(16) char smem[];
    const int tid = threadIdx.x, lane = tid & 31, wid = tid >> 5;
    const int g = blockIdx.x, row0 = blockIdx.y * 128;

    int r0q, r1q, r2q, r3q;
    if (MODE == 0)      { r0q = 64*g;     r1q = r0q + 32; r2q = 256 + 64*g; r3q = r2q + 32; }
    else if (MODE == 1) { r0q = 256+64*g; r1q = r0q + 32; r2q = 768 + 64*g; r3q = r2q + 32; }
    else                { r0q = 32*g;     r1q = 256+32*g; r2q = 512 + 32*g; r3q = 768 + 32*g; }

    int* srow = (int*)(smem + SM_SROW);
    if (tid < 128) {
        int gr = row0 + tid;
        if (gr >= M) gr = M - 1;
        srow[tid] = ids ? ids[gr] : gr;
    }
    __syncthreads();

    // cp.async loader mapping: 2 granules/thread/tile; granule g: row=g>>2, quad=g&3
    const int quad = tid & 3;
    const int rA0 = tid >> 2;          // rows 0..63
    const int rA1 = 64 + (tid >> 2);   // rows 64..127
    const uint32_t sb = smem_u32(smem);

    auto wrow_of = [&](int r) {
        int q = r >> 5;
        int base = (q == 0 ? r0q : q == 1 ? r1q : q == 2 ? r2q : r3q);
        return base + (r & 31);
    };
    const uint16_t* a0h = Ahi + (long long)srow[rA0] * MEM_C + quad * 8;
    const uint16_t* a0l = Alo + (long long)srow[rA0] * MEM_C + quad * 8;
    const uint16_t* a1h = Ahi + (long long)srow[rA1] * MEM_C + quad * 8;
    const uint16_t* a1l = Alo + (long long)srow[rA1] * MEM_C + quad * 8;
    const uint16_t* b0h = Whi + (long long)wrow_of(rA0) * MEM_C + quad * 8;
    const uint16_t* b0l = Wlo + (long long)wrow_of(rA0) * MEM_C + quad * 8;
    const uint16_t* b1h = Whi + (long long)wrow_of(rA1) * MEM_C + quad * 8;
    const uint16_t* b1l = Wlo + (long long)wrow_of(rA1) * MEM_C + quad * 8;
    const uint32_t dA0 = sb + ST_A_HI + rA0 * 80 + quad * 16;
    const uint32_t dA1 = sb + ST_A_HI + rA1 * 80 + quad * 16;
    const uint32_t dB0 = sb + ST_B_HI + rA0 * 80 + quad * 16;
    const uint32_t dB1 = sb + ST_B_HI + rA1 * 80 + quad * 16;

    // ldmatrix lane bases
    const int wm = wid >> 2, wn = wid & 3;
    const uint32_t aoff = sb + ST_A_HI +
        (64*wm + (lane & 7) + 8*((lane >> 3) & 1)) * 80 + (lane >> 4) * 16;
    const uint32_t boff0 = sb + ST_B_HI +
        (32*wn + (lane & 7) + (lane >> 4) * 8) * 80 + ((lane >> 3) & 1) * 16;
    const uint32_t boff1 = boff0 + 16 * 80;

    float acc[4][4][4];
#pragma unroll
    for (int i = 0; i < 4; ++i)
#pragma unroll
        for (int j = 0; j < 4; ++j)
#pragma unroll
            for (int e = 0; e < 4; ++e) acc[i][j][e] = 0.0f;

    auto issue = [&](int kb, uint32_t so) {
        CP16(dA0 + so,             a0h + kb);
        CP16(dA0 + so + 10240,     a0l + kb);
        CP16(dA1 + so,             a1h + kb);
        CP16(dA1 + so + 10240,     a1l + kb);
        CP16(dB0 + so,             b0h + kb);
        CP16(dB0 + so + 10240,     b0l + kb);
        CP16(dB1 + so,             b1h + kb);
        CP16(dB1 + so + 10240,     b1l + kb);
    };

    issue(0, 0);
    CP_COMMIT();

#pragma unroll 1
    for (int kc = 0; kc < 8; ++kc) {
        const uint32_t so = (uint32_t)(kc & 1) * ST_SIZE;
        if (kc < 7) {
            issue((kc + 1) * 32, (uint32_t)((kc + 1) & 1) * ST_SIZE);
            CP_COMMIT();
            CP_WAIT1();
        } else {
            CP_WAIT0();
        }
        __syncthreads();
#pragma unroll
        for (int kk = 0; kk < 2; ++kk) {
            uint32_t ka  = aoff  + so + kk * 32;
            uint32_t kb0 = boff0 + so + kk * 32;
            uint32_t kb1 = boff1 + so + kk * 32;
            uint32_t ah[4][4], al[4][4], bh[4][2], bl[4][2];
#pragma unroll
            for (int tm = 0; tm < 4; ++tm) {
                LDM4(ah[tm][0], ah[tm][1], ah[tm][2], ah[tm][3], ka + tm * 1280);
                LDM4(al[tm][0], al[tm][1], al[tm][2], al[tm][3], ka + tm * 1280 + 10240);
            }
            LDM4(bh[0][0], bh[0][1], bh[1][0], bh[1][1], kb0);
            LDM4(bh[2][0], bh[2][1], bh[3][0], bh[3][1], kb1);
            LDM4(bl[0][0], bl[0][1], bl[1][0], bl[1][1], kb0 + 10240);
            LDM4(bl[2][0], bl[2][1], bl[3][0], bl[3][1], kb1 + 10240);
#pragma unroll
            for (int tm = 0; tm < 4; ++tm)
#pragma unroll
                for (int tn = 0; tn < 4; ++tn) {
                    MMA_BF16(acc[tm][tn], ah[tm], bh[tn]);
                    MMA_BF16(acc[tm][tn], ah[tm], bl[tn]);
                    MMA_BF16(acc[tm][tn], al[tm], bh[tn]);
                }
        }
        __syncthreads();   // WAR: next issue() targets the buffer just read
    }

    // Stage D through smem, 132-float row stride
    float* Cs = (float*)smem;
#pragma unroll
    for (int tm = 0; tm < 4; ++tm)
#pragma unroll
        for (int tn = 0; tn < 4; ++tn) {
            int rr = 64*wm + 16*tm + (lane >> 2);
            int cc = 32*wn + 8*tn + 2*(lane & 3);
            Cs[rr * 132 + cc]       = acc[tm][tn][0];
            Cs[rr * 132 + cc + 1]   = acc[tm][tn][1];
            Cs[(rr+8) * 132 + cc]     = acc[tm][tn][2];
            Cs[(rr+8) * 132 + cc + 1] = acc[tm][tn][3];
        }
    __syncthreads();

    const int r = tid >> 1, seg = tid & 1;
    const int gb = row0 + r;
    if (gb < M) {
        if (MODE == 0) {
#pragma unroll
            for (int qq = 0; qq < 2; ++qq) {
                int qi = 2*seg + qq;
                int ob = (qi == 0 ? r0q : qi == 1 ? r1q : qi == 2 ? r2q : r3q);
#pragma unroll
                for (int jj = 0; jj < 32; jj += 4) {
                    float4 v  = *(float4*)&Cs[r * 132 + qi * 32 + jj];
                    float4 bv = *(const float4*)(bias + ob + jj);
                    v.x += bv.x; v.y += bv.y; v.z += bv.z; v.w += bv.w;
                    *(float4*)(C + (long long)gb * 512 + ob + jj) = v;
                }
            }
        } else if (MODE == 1) {
            int nid = srow[r];
            int c0 = r0q - 256;  // 64g
#pragma unroll
            for (int jj = 32*seg; jj < 32*seg + 32; jj += 4) {
                float4 hg4 = *(float4*)&Cs[r * 132 + jj];
                float4 ht4 = *(float4*)&Cs[r * 132 + 64 + jj];
                float4 bg = *(const float4*)(bias + r0q + jj);
                float4 bt = *(const float4*)(bias + r2q + jj);
                float4 xg = *(const float4*)(X + (long long)gb * 512 + c0 + jj);
                float4 xt = *(const float4*)(X + (long long)gb * 512 + r0q + jj);
                float4 mg = *(const float4*)(memv + (long long)nid * 256 + c0 + jj);
                float o[4];
                const float* HG = (const float*)&hg4; const float* HT = (const float*)&ht4;
                const float* BG = (const float*)&bg;  const float* BT = (const float*)&bt;
                const float* XG = (const float*)&xg;  const float* XT = (const float*)&xt;
                const float* MG = (const float*)&mg;
#pragma unroll
                for (int e = 0; e < 4; ++e) {
                    float gg = 1.0f / (1.0f + __expf(-(XG[e] + HG[e] + BG[e])));
                    float tt = tanhf(XT[e] + HT[e] + BT[e]);
                    o[e] = (1.0f - gg) * tt + gg * MG[e];
                }
                *(float4*)(memv + (long long)nid * 256 + c0 + jj) =
                    make_float4(o[0], o[1], o[2], o[3]);
                // refresh bf16 hi/lo copy for subsequent steps
                uint2 h, l;
                split4(make_float4(o[0], o[1], o[2], o[3]), h, l);
                *(uint2*)(mhi + (long long)nid * 256 + c0 + jj) = h;
                *(uint2*)(mlo + (long long)nid * 256 + c0 + jj) = l;
            }
        } else {
            int nid = srow[r];
            int c0 = r0q;  // 32g
#pragma unroll
            for (int jj = 16*seg; jj < 16*seg + 16; jj += 4) {
                float4 hgd = *(float4*)&Cs[r * 132 + jj];
                float4 hgc = *(float4*)&Cs[r * 132 + 32 + jj];
                float4 hhd = *(float4*)&Cs[r * 132 + 64 + jj];
                float4 hhc = *(float4*)&Cs[r * 132 + 96 + jj];
                float4 b0 = *(const float4*)(bias + r0q + jj);
                float4 b1 = *(const float4*)(bias + r1q + jj);
                float4 b2 = *(const float4*)(bias + r2q + jj);
                float4 b3 = *(const float4*)(bias + r3q + jj);
                float4 icg = *(const float4*)(X + (long long)gb * 512 + r0q + jj);
                float4 ich = *(const float4*)(X + (long long)gb * 512 + r1q + jj);
                float4 idg = *(const float4*)(Y + (long long)gb * 512 + r0q + jj);
                float4 idh = *(const float4*)(Y + (long long)gb * 512 + r1q + jj);
                float4 mg = *(const float4*)(memv + (long long)nid * 256 + c0 + jj);
                float o[4];
                const float* P0 = (const float*)&hgd; const float* P1 = (const float*)&hgc;
                const float* P2 = (const float*)&hhd; const float* P3 = (const float*)&hhc;
                const float* B0 = (const float*)&b0;  const float* B1 = (const float*)&b1;
                const float* B2 = (const float*)&b2;  const float* B3 = (const float*)&b3;
                const float* ICG = (const float*)&icg; const float* ICH = (const float*)&ich;
                const float* IDG = (const float*)&idg; const float* IDH = (const float*)&idh;
                const float* MG = (const float*)&mg;
#pragma unroll
                for (int e = 0; e < 4; ++e) {
                    float GD = 1.0f / (1.0f + __expf(-(IDG[e] + P0[e] + B0[e])));
                    float GC = 1.0f / (1.0f + __expf(-(ICG[e] + P1[e] + B1[e])));
                    float hD = tanhf(IDH[e] + P2[e] + B2[e]);
                    float hC = tanhf(ICH[e] + P3[e] + B3[e]);
                    o[e] = 0.5f * (GD * hD + GC * hC + (2.0f - GD - GC) * MG[e]);
                }
                *(float4*)(memv + (long long)nid * 256 + c0 + jj) =
                    make_float4(o[0], o[1], o[2], o[3]);
            }
        }
    }
}

// ---------------------------------------------------------------------------
extern "C" void kernel_launch(void* const* d_in, const int* in_sizes, int n_in,
                              void* d_out, int out_size)
{
    const float* memory   = (const float*)d_in[0];
    const void*  node_raw = d_in[1];
    const float* messages = (const float*)d_in[2];
    const float* dtdg     = (const float*)d_in[3];
    const float* WCw      = (const float*)d_in[4];
    const float* WCb      = (const float*)d_in[5];
    const float* WDw      = (const float*)d_in[6];
    const float* WDb      = (const float*)d_in[7];
    const float* Whw      = (const float*)d_in[8];
    const float* Whb      = (const float*)d_in[9];
    float* mem = (float*)d_out;

    float *IC, *IDb; int *IDS;
    uint16_t *MSGhi, *MSGlo, *MEMhi, *MEMlo, *DThi, *DTlo;
    uint16_t *WChi, *WClo, *WDhi, *WDlo, *Whhi, *Whlo;
    cudaGetSymbolAddress((void**)&IC,    g_IC);
    cudaGetSymbolAddress((void**)&IDb,   g_ID);
    cudaGetSymbolAddress((void**)&IDS,   g_IDS);
    cudaGetSymbolAddress((void**)&MSGhi, g_MSGhi);
    cudaGetSymbolAddress((void**)&MSGlo, g_MSGlo);
    cudaGetSymbolAddress((void**)&MEMhi, g_MEMhi);
    cudaGetSymbolAddress((void**)&MEMlo, g_MEMlo);
    cudaGetSymbolAddress((void**)&DThi,  g_DThi);
    cudaGetSymbolAddress((void**)&DTlo,  g_DTlo);
    cudaGetSymbolAddress((void**)&WChi,  g_WChi);
    cudaGetSymbolAddress((void**)&WClo,  g_WClo);
    cudaGetSymbolAddress((void**)&WDhi,  g_WDhi);
    cudaGetSymbolAddress((void**)&WDlo,  g_WDlo);
    cudaGetSymbolAddress((void**)&Whhi,  g_Whhi);
    cudaGetSymbolAddress((void**)&Whlo,  g_Whlo);

    cudaFuncSetAttribute(mma_gemm<0>, cudaFuncAttributeMaxDynamicSharedMemorySize, SM_TOTAL);
    cudaFuncSetAttribute(mma_gemm<1>, cudaFuncAttributeMaxDynamicSharedMemorySize, SM_TOTAL);
    cudaFuncSetAttribute(mma_gemm<2>, cudaFuncAttributeMaxDynamicSharedMemorySize, SM_TOTAL);

    cudaMemcpyAsync(mem, memory, (size_t)N_NODES_C * MEM_C * sizeof(float),
                    cudaMemcpyDeviceToDevice);

    normalize_ids<<<(DIV_C * B_C + 255) / 256, 256>>>(
        (const unsigned int*)node_raw, IDS, DIV_C * B_C);

    // Preconvert operands to bf16 hi/lo
    const long long n4_msg = (long long)DIV_C * B_C * MEM_C / 4;
    const long long n4_mem = (long long)N_NODES_C * MEM_C / 4;
    cvt_split<<<(int)((n4_msg + 255) / 256), 256>>>(messages, MSGhi, MSGlo, n4_msg);
    cvt_split<<<(int)((n4_mem + 255) / 256), 256>>>(memory, MEMhi, MEMlo, n4_mem);
    cvt_split<<<(512 * MEM_C / 4 + 255) / 256, 256>>>(WCw, WChi, WClo, 512 * MEM_C / 4);
    cvt_split<<<(512 * MEM_C / 4 + 255) / 256, 256>>>(WDw, WDhi, WDlo, 512 * MEM_C / 4);
    cvt_split<<<(1024 * MEM_C / 4 + 255) / 256, 256>>>(Whw, Whhi, Whlo, 1024 * MEM_C / 4);

    const int* ids7 = IDS + (DIV_C - 1) * B_C;
    cvt_gather<<<(B_C * 64 + 255) / 256, 256>>>(dtdg, ids7, DThi, DTlo);

    const int gy = (B_C + 127) / 128;  // 157

    // i_C for all 8 steps
    mma_gemm<0><<<dim3(4, (DIV_C * B_C) / 128), 256, SM_TOTAL>>>(
        MSGhi, MSGlo, nullptr, DIV_C * B_C, WChi, WClo, WCb,
        nullptr, nullptr, IC, nullptr, nullptr, nullptr);

    // i_D for the final step (compact-gathered dtdg rows)
    mma_gemm<0><<<dim3(4, gy), 256, SM_TOTAL>>>(
        DThi, DTlo, nullptr, B_C, WDhi, WDlo, WDb,
        nullptr, nullptr, IDb, nullptr, nullptr, nullptr);

    // 7 regular steps, in-place mem update (+ hi/lo refresh)
    for (int s = 0; s < DIV_C - 1; ++s) {
        mma_gemm<1><<<dim3(4, gy), 256, SM_TOTAL>>>(
            MEMhi, MEMlo, IDS + s * B_C, B_C, Whhi, Whlo, Whb,
            IC + (long long)s * B_C * 512, nullptr, nullptr, mem, MEMhi, MEMlo);
    }
    // Final step, fully fused (all 4 slices)
    mma_gemm<2><<<dim3(8, gy), 256, SM_TOTAL>>>(
        MEMhi, MEMlo, ids7, B_C, Whhi, Whlo, Whb,
        IC + (long long)(DIV_C - 1) * B_C * 512, IDb, nullptr, mem, nullptr, nullptr);
}

// round 9
// speedup vs baseline: 2.0403x; 1.0056x over previous
#include <cuda_runtime.h>
#include <cuda_bf16.h>
#include <cstdint>

#define MEM_C 256
#define B_C 20000
#define DIV_C 8
#define N_NODES_C 100000

// Stage layout (bytes): bf16 tiles, 80B row stride (64B data + 16 pad)
#define ST_A_HI 0
#define ST_A_LO 10240
#define ST_B_HI 20480
#define ST_B_LO 30720
#define ST_SIZE 40960
#define SM_SROW 81920
#define SM_TOTAL (81920 + 640)

// Scratch (device globals: allocation-free per harness rules)
__device__ float    g_IC[DIV_C * (long long)B_C * 512];
__device__ float    g_ID[(long long)B_C * 512];
__device__ int      g_IDS[DIV_C * B_C];
__device__ uint16_t g_MSGhi[DIV_C * (long long)B_C * MEM_C];
__device__ uint16_t g_MSGlo[DIV_C * (long long)B_C * MEM_C];
__device__ uint16_t g_MEMhi[(long long)N_NODES_C * MEM_C];
__device__ uint16_t g_MEMlo[(long long)N_NODES_C * MEM_C];
__device__ uint16_t g_DThi[(long long)B_C * MEM_C];
__device__ uint16_t g_DTlo[(long long)B_C * MEM_C];
__device__ uint16_t g_WChi[512 * MEM_C], g_WClo[512 * MEM_C];
__device__ uint16_t g_WDhi[512 * MEM_C], g_WDlo[512 * MEM_C];
__device__ uint16_t g_Whhi[1024 * MEM_C], g_Whlo[1024 * MEM_C];

__device__ __forceinline__ uint32_t smem_u32(const void* p) {
    uint32_t a;
    asm("{ .reg .u64 t; cvta.to.shared.u64 t, %1; cvt.u32.u64 %0, t; }" : "=r"(a) : "l"(p));
    return a;
}

#define LDM4(r0, r1, r2, r3, addr)                                          \
    asm volatile("ldmatrix.sync.aligned.m8n8.x4.shared.b16 {%0,%1,%2,%3}, [%4];" \
                 : "=r"(r0), "=r"(r1), "=r"(r2), "=r"(r3) : "r"(addr))

#define MMA_BF16(c, a, b)                                                   \
    asm volatile("mma.sync.aligned.m16n8k16.row.col.f32.bf16.bf16.f32 "     \
                 "{%0,%1,%2,%3},{%4,%5,%6,%7},{%8,%9},{%0,%1,%2,%3};"       \
                 : "+f"((c)[0]), "+f"((c)[1]), "+f"((c)[2]), "+f"((c)[3])   \
                 : "r"((a)[0]), "r"((a)[1]), "r"((a)[2]), "r"((a)[3]),      \
                   "r"((b)[0]), "r"((b)[1]))

#define CP16(dst, src)                                                      \
    asm volatile("cp.async.cg.shared.global [%0], [%1], 16;"                \
                 :: "r"(dst), "l"(src))
#define CP_COMMIT() asm volatile("cp.async.commit_group;" ::: "memory")
#define CP_WAIT1()  asm volatile("cp.async.wait_group 1;" ::: "memory")
#define CP_WAIT0()  asm volatile("cp.async.wait_group 0;" ::: "memory")

__global__ void normalize_ids(const unsigned int* __restrict__ raw,
                              int* __restrict__ out, int n)
{
    const bool is64 = (raw[1] == 0u) && (raw[3] == 0u);
    int t = blockIdx.x * blockDim.x + threadIdx.x;
    if (t < n) out[t] = is64 ? (int)raw[2 * t] : (int)raw[t];
}

// fp32 -> bf16 hi/lo split, vectorized float4 per thread
__device__ __forceinline__ void split4(float4 v, uint2& h, uint2& l)
{
    __nv_bfloat162 h01 = __floats2bfloat162_rn(v.x, v.y);
    __nv_bfloat162 h23 = __floats2bfloat162_rn(v.z, v.w);
    float rx = v.x - __bfloat162float(__low2bfloat16(h01));
    float ry = v.y - __bfloat162float(__high2bfloat16(h01));
    float rz = v.z - __bfloat162float(__low2bfloat16(h23));
    float rw = v.w - __bfloat162float(__high2bfloat16(h23));
    __nv_bfloat162 l01 = __floats2bfloat162_rn(rx, ry);
    __nv_bfloat162 l23 = __floats2bfloat162_rn(rz, rw);
    h = make_uint2(*(uint32_t*)&h01, *(uint32_t*)&h23);
    l = make_uint2(*(uint32_t*)&l01, *(uint32_t*)&l23);
}

__global__ void cvt_split(const float* __restrict__ src, uint16_t* __restrict__ hi,
                          uint16_t* __restrict__ lo, long long n4)
{
    long long t = (long long)blockIdx.x * blockDim.x + threadIdx.x;
    if (t >= n4) return;
    uint2 h, l;
    split4(reinterpret_cast<const float4*>(src)[t], h, l);
    reinterpret_cast<uint2*>(hi)[t] = h;
    reinterpret_cast<uint2*>(lo)[t] = l;
}

// Gather-convert B_C rows (compact output)
__global__ void cvt_gather(const float* __restrict__ src, const int* __restrict__ ids,
                           uint16_t* __restrict__ hi, uint16_t* __restrict__ lo)
{
    int t = blockIdx.x * blockDim.x + threadIdx.x;
    if (t >= B_C * 64) return;
    int b = t >> 6, q = t & 63;
    uint2 h, l;
    split4(*(const float4*)(src + (long long)ids[b] * MEM_C + q * 4), h, l);
    reinterpret_cast<uint2*>(hi)[(long long)b * 64 + q] = h;
    reinterpret_cast<uint2*>(lo)[(long long)b * 64 + q] = l;
}

// ---------------------------------------------------------------------------
// Unified mma.sync bf16-split GEMM engine, cp.async double-buffered.
// MMA stream is TERM-MAJOR (all hh, then all hl, then all lh) so consecutive
// HMMAs hit distinct accumulators: no RAW chains in the volatile asm stream.
// MODE 0: C[gb][quarters] = D + bias      (IC / ID precompute)
// MODE 1: regular step (slices 1,3), in-place mem update + hi/lo refresh
// MODE 2: final step fully fused (all 4 slices), in-place update
// ---------------------------------------------------------------------------
template<int MODE>
__global__ __launch_bounds__(256, 2)
void mma_gemm(const uint16_t* __restrict__ Ahi, const uint16_t* __restrict__ Alo,
              const int* __restrict__ ids, int M,
              const uint16_t* __restrict__ Whi, const uint16_t* __restrict__ Wlo,
              const float* __restrict__ bias,
              const float* __restrict__ X, const float* __restrict__ Y,
              float* __restrict__ C, float* __restrict__ memv,
              uint16_t* __restrict__ mhi, uint16_t* __restrict__ mlo)
{
    extern __shared__ __align__(16) char smem[];
    const int tid = threadIdx.x, lane = tid & 31, wid = tid >> 5;
    const int g = blockIdx.x, row0 = blockIdx.y * 128;

    int r0q, r1q, r2q, r3q;
    if (MODE == 0)      { r0q = 64*g;     r1q = r0q + 32; r2q = 256 + 64*g; r3q = r2q + 32; }
    else if (MODE == 1) { r0q = 256+64*g; r1q = r0q + 32; r2q = 768 + 64*g; r3q = r2q + 32; }
    else                { r0q = 32*g;     r1q = 256+32*g; r2q = 512 + 32*g; r3q = 768 + 32*g; }

    int* srow = (int*)(smem + SM_SROW);
    if (tid < 128) {
        int gr = row0 + tid;
        if (gr >= M) gr = M - 1;
        srow[tid] = ids ? ids[gr] : gr;
    }
    __syncthreads();

    // cp.async loader mapping
    const int quad = tid & 3;
    const int rA0 = tid >> 2;          // rows 0..63
    const int rA1 = 64 + (tid >> 2);   // rows 64..127
    const uint32_t sb = smem_u32(smem);

    auto wrow_of = [&](int r) {
        int q = r >> 5;
        int base = (q == 0 ? r0q : q == 1 ? r1q : q == 2 ? r2q : r3q);
        return base + (r & 31);
    };
    const uint16_t* a0h = Ahi + (long long)srow[rA0] * MEM_C + quad * 8;
    const uint16_t* a0l = Alo + (long long)srow[rA0] * MEM_C + quad * 8;
    const uint16_t* a1h = Ahi + (long long)srow[rA1] * MEM_C + quad * 8;
    const uint16_t* a1l = Alo + (long long)srow[rA1] * MEM_C + quad * 8;
    const uint16_t* b0h = Whi + (long long)wrow_of(rA0) * MEM_C + quad * 8;
    const uint16_t* b0l = Wlo + (long long)wrow_of(rA0) * MEM_C + quad * 8;
    const uint16_t* b1h = Whi + (long long)wrow_of(rA1) * MEM_C + quad * 8;
    const uint16_t* b1l = Wlo + (long long)wrow_of(rA1) * MEM_C + quad * 8;
    const uint32_t dA0 = sb + ST_A_HI + rA0 * 80 + quad * 16;
    const uint32_t dA1 = sb + ST_A_HI + rA1 * 80 + quad * 16;
    const uint32_t dB0 = sb + ST_B_HI + rA0 * 80 + quad * 16;
    const uint32_t dB1 = sb + ST_B_HI + rA1 * 80 + quad * 16;

    // ldmatrix lane bases
    const int wm = wid >> 2, wn = wid & 3;
    const uint32_t aoff = sb + ST_A_HI +
        (64*wm + (lane & 7) + 8*((lane >> 3) & 1)) * 80 + (lane >> 4) * 16;
    const uint32_t boff0 = sb + ST_B_HI +
        (32*wn + (lane & 7) + (lane >> 4) * 8) * 80 + ((lane >> 3) & 1) * 16;
    const uint32_t boff1 = boff0 + 16 * 80;

    float acc[4][4][4];
#pragma unroll
    for (int i = 0; i < 4; ++i)
#pragma unroll
        for (int j = 0; j < 4; ++j)
#pragma unroll
            for (int e = 0; e < 4; ++e) acc[i][j][e] = 0.0f;

    auto issue = [&](int kb, uint32_t so) {
        CP16(dA0 + so,             a0h + kb);
        CP16(dA0 + so + 10240,     a0l + kb);
        CP16(dA1 + so,             a1h + kb);
        CP16(dA1 + so + 10240,     a1l + kb);
        CP16(dB0 + so,             b0h + kb);
        CP16(dB0 + so + 10240,     b0l + kb);
        CP16(dB1 + so,             b1h + kb);
        CP16(dB1 + so + 10240,     b1l + kb);
    };

    issue(0, 0);
    CP_COMMIT();

#pragma unroll 1
    for (int kc = 0; kc < 8; ++kc) {
        const uint32_t so = (uint32_t)(kc & 1) * ST_SIZE;
        if (kc < 7) {
            issue((kc + 1) * 32, (uint32_t)((kc + 1) & 1) * ST_SIZE);
            CP_COMMIT();
            CP_WAIT1();
        } else {
            CP_WAIT0();
        }
        __syncthreads();
#pragma unroll
        for (int kk = 0; kk < 2; ++kk) {
            uint32_t ka  = aoff  + so + kk * 32;
            uint32_t kb0 = boff0 + so + kk * 32;
            uint32_t kb1 = boff1 + so + kk * 32;
            uint32_t ah[4][4], al[4][4], bh[4][2], bl[4][2];
#pragma unroll
            for (int tm = 0; tm < 4; ++tm) {
                LDM4(ah[tm][0], ah[tm][1], ah[tm][2], ah[tm][3], ka + tm * 1280);
                LDM4(al[tm][0], al[tm][1], al[tm][2], al[tm][3], ka + tm * 1280 + 10240);
            }
            LDM4(bh[0][0], bh[0][1], bh[1][0], bh[1][1], kb0);
            LDM4(bh[2][0], bh[2][1], bh[3][0], bh[3][1], kb1);
            LDM4(bl[0][0], bl[0][1], bl[1][0], bl[1][1], kb0 + 10240);
            LDM4(bl[2][0], bl[2][1], bl[3][0], bl[3][1], kb1 + 10240);
            // Term-major: consecutive HMMAs use distinct accumulators.
            // Per-acc add order is still hh, hl, lh (numerics unchanged).
#pragma unroll
            for (int tm = 0; tm < 4; ++tm)
#pragma unroll
                for (int tn = 0; tn < 4; ++tn)
                    MMA_BF16(acc[tm][tn], ah[tm], bh[tn]);
#pragma unroll
            for (int tm = 0; tm < 4; ++tm)
#pragma unroll
                for (int tn = 0; tn < 4; ++tn)
                    MMA_BF16(acc[tm][tn], ah[tm], bl[tn]);
#pragma unroll
            for (int tm = 0; tm < 4; ++tm)
#pragma unroll
                for (int tn = 0; tn < 4; ++tn)
                    MMA_BF16(acc[tm][tn], al[tm], bh[tn]);
        }
        __syncthreads();   // WAR: next issue() targets the buffer just read
    }

    // Stage D through smem, 132-float row stride
    float* Cs = (float*)smem;
#pragma unroll
    for (int tm = 0; tm < 4; ++tm)
#pragma unroll
        for (int tn = 0; tn < 4; ++tn) {
            int rr = 64*wm + 16*tm + (lane >> 2);
            int cc = 32*wn + 8*tn + 2*(lane & 3);
            Cs[rr * 132 + cc]       = acc[tm][tn][0];
            Cs[rr * 132 + cc + 1]   = acc[tm][tn][1];
            Cs[(rr+8) * 132 + cc]     = acc[tm][tn][2];
            Cs[(rr+8) * 132 + cc + 1] = acc[tm][tn][3];
        }
    __syncthreads();

    const int r = tid >> 1, seg = tid & 1;
    const int gb = row0 + r;
    if (gb < M) {
        if (MODE == 0) {
#pragma unroll
            for (int qq = 0; qq < 2; ++qq) {
                int qi = 2*seg + qq;
                int ob = (qi == 0 ? r0q : qi == 1 ? r1q : qi == 2 ? r2q : r3q);
#pragma unroll
                for (int jj = 0; jj < 32; jj += 4) {
                    float4 v  = *(float4*)&Cs[r * 132 + qi * 32 + jj];
                    float4 bv = *(const float4*)(bias + ob + jj);
                    v.x += bv.x; v.y += bv.y; v.z += bv.z; v.w += bv.w;
                    *(float4*)(C + (long long)gb * 512 + ob + jj) = v;
                }
            }
        } else if (MODE == 1) {
            int nid = srow[r];
            int c0 = r0q - 256;  // 64g
#pragma unroll
            for (int jj = 32*seg; jj < 32*seg + 32; jj += 4) {
                float4 hg4 = *(float4*)&Cs[r * 132 + jj];
                float4 ht4 = *(float4*)&Cs[r * 132 + 64 + jj];
                float4 bg = *(const float4*)(bias + r0q + jj);
                float4 bt = *(const float4*)(bias + r2q + jj);
                float4 xg = *(const float4*)(X + (long long)gb * 512 + c0 + jj);
                float4 xt = *(const float4*)(X + (long long)gb * 512 + r0q + jj);
                float4 mg = *(const float4*)(memv + (long long)nid * 256 + c0 + jj);
                float o[4];
                const float* HG = (const float*)&hg4; const float* HT = (const float*)&ht4;
                const float* BG = (const float*)&bg;  const float* BT = (const float*)&bt;
                const float* XG = (const float*)&xg;  const float* XT = (const float*)&xt;
                const float* MG = (const float*)&mg;
#pragma unroll
                for (int e = 0; e < 4; ++e) {
                    float gg = 1.0f / (1.0f + __expf(-(XG[e] + HG[e] + BG[e])));
                    float tt = tanhf(XT[e] + HT[e] + BT[e]);
                    o[e] = (1.0f - gg) * tt + gg * MG[e];
                }
                *(float4*)(memv + (long long)nid * 256 + c0 + jj) =
                    make_float4(o[0], o[1], o[2], o[3]);
                // refresh bf16 hi/lo copy for subsequent steps
                uint2 h, l;
                split4(make_float4(o[0], o[1], o[2], o[3]), h, l);
                *(uint2*)(mhi + (long long)nid * 256 + c0 + jj) = h;
                *(uint2*)(mlo + (long long)nid * 256 + c0 + jj) = l;
            }
        } else {
            int nid = srow[r];
            int c0 = r0q;  // 32g
#pragma unroll
            for (int jj = 16*seg; jj < 16*seg + 16; jj += 4) {
                float4 hgd = *(float4*)&Cs[r * 132 + jj];
                float4 hgc = *(float4*)&Cs[r * 132 + 32 + jj];
                float4 hhd = *(float4*)&Cs[r * 132 + 64 + jj];
                float4 hhc = *(float4*)&Cs[r * 132 + 96 + jj];
                float4 b0 = *(const float4*)(bias + r0q + jj);
                float4 b1 = *(const float4*)(bias + r1q + jj);
                float4 b2 = *(const float4*)(bias + r2q + jj);
                float4 b3 = *(const float4*)(bias + r3q + jj);
                float4 icg = *(const float4*)(X + (long long)gb * 512 + r0q + jj);
                float4 ich = *(const float4*)(X + (long long)gb * 512 + r1q + jj);
                float4 idg = *(const float4*)(Y + (long long)gb * 512 + r0q + jj);
                float4 idh = *(const float4*)(Y + (long long)gb * 512 + r1q + jj);
                float4 mg = *(const float4*)(memv + (long long)nid * 256 + c0 + jj);
                float o[4];
                const float* P0 = (const float*)&hgd; const float* P1 = (const float*)&hgc;
                const float* P2 = (const float*)&hhd; const float* P3 = (const float*)&hhc;
                const float* B0 = (const float*)&b0;  const float* B1 = (const float*)&b1;
                const float* B2 = (const float*)&b2;  const float* B3 = (const float*)&b3;
                const float* ICG = (const float*)&icg; const float* ICH = (const float*)&ich;
                const float* IDG = (const float*)&idg; const float* IDH = (const float*)&idh;
                const float* MG = (const float*)&mg;
#pragma unroll
                for (int e = 0; e < 4; ++e) {
                    float GD = 1.0f / (1.0f + __expf(-(IDG[e] + P0[e] + B0[e])));
                    float GC = 1.0f / (1.0f + __expf(-(ICG[e] + P1[e] + B1[e])));
                    float hD = tanhf(IDH[e] + P2[e] + B2[e]);
                    float hC = tanhf(ICH[e] + P3[e] + B3[e]);
                    o[e] = 0.5f * (GD * hD + GC * hC + (2.0f - GD - GC) * MG[e]);
                }
                *(float4*)(memv + (long long)nid * 256 + c0 + jj) =
                    make_float4(o[0], o[1], o[2], o[3]);
            }
        }
    }
}

// ---------------------------------------------------------------------------
extern "C" void kernel_launch(void* const* d_in, const int* in_sizes, int n_in,
                              void* d_out, int out_size)
{
    const float* memory   = (const float*)d_in[0];
    const void*  node_raw = d_in[1];
    const float* messages = (const float*)d_in[2];
    const float* dtdg     = (const float*)d_in[3];
    const float* WCw      = (const float*)d_in[4];
    const float* WCb      = (const float*)d_in[5];
    const float* WDw      = (const float*)d_in[6];
    const float* WDb      = (const float*)d_in[7];
    const float* Whw      = (const float*)d_in[8];
    const float* Whb      = (const float*)d_in[9];
    float* mem = (float*)d_out;

    float *IC, *IDb; int *IDS;
    uint16_t *MSGhi, *MSGlo, *MEMhi, *MEMlo, *DThi, *DTlo;
    uint16_t *WChi, *WClo, *WDhi, *WDlo, *Whhi, *Whlo;
    cudaGetSymbolAddress((void**)&IC,    g_IC);
    cudaGetSymbolAddress((void**)&IDb,   g_ID);
    cudaGetSymbolAddress((void**)&IDS,   g_IDS);
    cudaGetSymbolAddress((void**)&MSGhi, g_MSGhi);
    cudaGetSymbolAddress((void**)&MSGlo, g_MSGlo);
    cudaGetSymbolAddress((void**)&MEMhi, g_MEMhi);
    cudaGetSymbolAddress((void**)&MEMlo, g_MEMlo);
    cudaGetSymbolAddress((void**)&DThi,  g_DThi);
    cudaGetSymbolAddress((void**)&DTlo,  g_DTlo);
    cudaGetSymbolAddress((void**)&WChi,  g_WChi);
    cudaGetSymbolAddress((void**)&WClo,  g_WClo);
    cudaGetSymbolAddress((void**)&WDhi,  g_WDhi);
    cudaGetSymbolAddress((void**)&WDlo,  g_WDlo);
    cudaGetSymbolAddress((void**)&Whhi,  g_Whhi);
    cudaGetSymbolAddress((void**)&Whlo,  g_Whlo);

    cudaFuncSetAttribute(mma_gemm<0>, cudaFuncAttributeMaxDynamicSharedMemorySize, SM_TOTAL);
    cudaFuncSetAttribute(mma_gemm<1>, cudaFuncAttributeMaxDynamicSharedMemorySize, SM_TOTAL);
    cudaFuncSetAttribute(mma_gemm<2>, cudaFuncAttributeMaxDynamicSharedMemorySize, SM_TOTAL);

    cudaMemcpyAsync(mem, memory, (size_t)N_NODES_C * MEM_C * sizeof(float),
                    cudaMemcpyDeviceToDevice);

    normalize_ids<<<(DIV_C * B_C + 255) / 256, 256>>>(
        (const unsigned int*)node_raw, IDS, DIV_C * B_C);

    // Preconvert operands to bf16 hi/lo
    const long long n4_msg = (long long)DIV_C * B_C * MEM_C / 4;
    const long long n4_mem = (long long)N_NODES_C * MEM_C / 4;
    cvt_split<<<(int)((n4_msg + 255) / 256), 256>>>(messages, MSGhi, MSGlo, n4_msg);
    cvt_split<<<(int)((n4_mem + 255) / 256), 256>>>(memory, MEMhi, MEMlo, n4_mem);
    cvt_split<<<(512 * MEM_C / 4 + 255) / 256, 256>>>(WCw, WChi, WClo, 512 * MEM_C / 4);
    cvt_split<<<(512 * MEM_C / 4 + 255) / 256, 256>>>(WDw, WDhi, WDlo, 512 * MEM_C / 4);
    cvt_split<<<(1024 * MEM_C / 4 + 255) / 256, 256>>>(Whw, Whhi, Whlo, 1024 * MEM_C / 4);

    const int* ids7 = IDS + (DIV_C - 1) * B_C;
    cvt_gather<<<(B_C * 64 + 255) / 256, 256>>>(dtdg, ids7, DThi, DTlo);

    const int gy = (B_C + 127) / 128;  // 157

    // i_C for all 8 steps
    mma_gemm<0><<<dim3(4, (DIV_C * B_C) / 128), 256, SM_TOTAL>>>(
        MSGhi, MSGlo, nullptr, DIV_C * B_C, WChi, WClo, WCb,
        nullptr, nullptr, IC, nullptr, nullptr, nullptr);

    // i_D for the final step (compact-gathered dtdg rows)
    mma_gemm<0><<<dim3(4, gy), 256, SM_TOTAL>>>(
        DThi, DTlo, nullptr, B_C, WDhi, WDlo, WDb,
        nullptr, nullptr, IDb, nullptr, nullptr, nullptr);

    // 7 regular steps, in-place mem update (+ hi/lo refresh)
    for (int s = 0; s < DIV_C - 1; ++s) {
        mma_gemm<1><<<dim3(4, gy), 256, SM_TOTAL>>>(
            MEMhi, MEMlo, IDS + s * B_C, B_C, Whhi, Whlo, Whb,
            IC + (long long)s * B_C * 512, nullptr, nullptr, mem, MEMhi, MEMlo);
    }
    // Final step, fully fused (all 4 slices)
    mma_gemm<2><<<dim3(8, gy), 256, SM_TOTAL>>>(
        MEMhi, MEMlo, ids7, B_C, Whhi, Whlo, Whb,
        IC + (long long)(DIV_C - 1) * B_C * 512, IDb, nullptr, mem, nullptr, nullptr);
}

// round 11
// speedup vs baseline: 2.3225x; 1.1383x over previous
#include <cuda_runtime.h>
#include <cuda_bf16.h>
#include <cstdint>

#define MEM_C 256
#define B_C 20000
#define DIV_C 8
#define N_NODES_C 100000

// Stage layout (bytes): bf16 tiles, 80B row stride (64B data + 16 pad)
#define ST_A_HI 0
#define ST_A_LO 10240
#define ST_B_HI 20480
#define ST_B_LO 30720
#define ST_SIZE 40960
#define SM_SROW 81920
#define SM_TOTAL (81920 + 640)

// Scratch (device globals: allocation-free per harness rules)
__device__ float    g_IC[DIV_C * (long long)B_C * 512];
__device__ float    g_ID[(long long)B_C * 512];
__device__ int      g_IDS[DIV_C * B_C];
__device__ uint16_t g_MSGhi[DIV_C * (long long)B_C * MEM_C];
__device__ uint16_t g_MSGlo[DIV_C * (long long)B_C * MEM_C];
__device__ uint16_t g_MEMhi[(long long)N_NODES_C * MEM_C];
__device__ uint16_t g_MEMlo[(long long)N_NODES_C * MEM_C];
__device__ uint16_t g_DThi[(long long)B_C * MEM_C];
__device__ uint16_t g_DTlo[(long long)B_C * MEM_C];
__device__ uint16_t g_WChi[512 * MEM_C], g_WClo[512 * MEM_C];
__device__ uint16_t g_WDhi[512 * MEM_C], g_WDlo[512 * MEM_C];
__device__ uint16_t g_Whhi[1024 * MEM_C], g_Whlo[1024 * MEM_C];

__device__ __forceinline__ uint32_t smem_u32(const void* p) {
    uint32_t a;
    asm("{ .reg .u64 t; cvta.to.shared.u64 t, %1; cvt.u32.u64 %0, t; }" : "=r"(a) : "l"(p));
    return a;
}

#define LDM4(r0, r1, r2, r3, addr)                                          \
    asm volatile("ldmatrix.sync.aligned.m8n8.x4.shared.b16 {%0,%1,%2,%3}, [%4];" \
                 : "=r"(r0), "=r"(r1), "=r"(r2), "=r"(r3) : "r"(addr))

// Non-volatile: pure register op, lets ptxas schedule HMMAs freely.
#define MMA_BF16(c, a, b)                                                   \
    asm("mma.sync.aligned.m16n8k16.row.col.f32.bf16.bf16.f32 "              \
        "{%0,%1,%2,%3},{%4,%5,%6,%7},{%8,%9},{%0,%1,%2,%3};"                \
        : "+f"((c)[0]), "+f"((c)[1]), "+f"((c)[2]), "+f"((c)[3])            \
        : "r"((a)[0]), "r"((a)[1]), "r"((a)[2]), "r"((a)[3]),               \
          "r"((b)[0]), "r"((b)[1]))

#define CP16(dst, src)                                                      \
    asm volatile("cp.async.cg.shared.global [%0], [%1], 16;"                \
                 :: "r"(dst), "l"(src))
#define CP_COMMIT() asm volatile("cp.async.commit_group;" ::: "memory")
#define CP_WAIT1()  asm volatile("cp.async.wait_group 1;" ::: "memory")
#define CP_WAIT0()  asm volatile("cp.async.wait_group 0;" ::: "memory")

__global__ void normalize_ids(const unsigned int* __restrict__ raw,
                              int* __restrict__ out, int n)
{
    const bool is64 = (raw[1] == 0u) && (raw[3] == 0u);
    int t = blockIdx.x * blockDim.x + threadIdx.x;
    if (t < n) out[t] = is64 ? (int)raw[2 * t] : (int)raw[t];
}

// fp32 -> bf16 hi/lo split, vectorized float4 per thread
__device__ __forceinline__ void split4(float4 v, uint2& h, uint2& l)
{
    __nv_bfloat162 h01 = __floats2bfloat162_rn(v.x, v.y);
    __nv_bfloat162 h23 = __floats2bfloat162_rn(v.z, v.w);
    float rx = v.x - __bfloat162float(__low2bfloat16(h01));
    float ry = v.y - __bfloat162float(__high2bfloat16(h01));
    float rz = v.z - __bfloat162float(__low2bfloat16(h23));
    float rw = v.w - __bfloat162float(__high2bfloat16(h23));
    __nv_bfloat162 l01 = __floats2bfloat162_rn(rx, ry);
    __nv_bfloat162 l23 = __floats2bfloat162_rn(rz, rw);
    h = make_uint2(*(uint32_t*)&h01, *(uint32_t*)&h23);
    l = make_uint2(*(uint32_t*)&l01, *(uint32_t*)&l23);
}

__global__ void cvt_split(const float* __restrict__ src, uint16_t* __restrict__ hi,
                          uint16_t* __restrict__ lo, long long n4)
{
    long long t = (long long)blockIdx.x * blockDim.x + threadIdx.x;
    if (t >= n4) return;
    uint2 h, l;
    split4(reinterpret_cast<const float4*>(src)[t], h, l);
    reinterpret_cast<uint2*>(hi)[t] = h;
    reinterpret_cast<uint2*>(lo)[t] = l;
}

// Gather-convert B_C rows (compact output)
__global__ void cvt_gather(const float* __restrict__ src, const int* __restrict__ ids,
                           uint16_t* __restrict__ hi, uint16_t* __restrict__ lo)
{
    int t = blockIdx.x * blockDim.x + threadIdx.x;
    if (t >= B_C * 64) return;
    int b = t >> 6, q = t & 63;
    uint2 h, l;
    split4(*(const float4*)(src + (long long)ids[b] * MEM_C + q * 4), h, l);
    reinterpret_cast<uint2*>(hi)[(long long)b * 64 + q] = h;
    reinterpret_cast<uint2*>(lo)[(long long)b * 64 + q] = l;
}

// Refresh bf16 hi/lo mirror for the rows updated by a step (in-place offsets).
// Runs AFTER the step kernel: kernel-boundary ordering kills the intra-step
// race between sibling-CTA epilogue writes and mainloop gathers.
__global__ void refresh_rows(const float* __restrict__ mem, const int* __restrict__ ids,
                             uint16_t* __restrict__ hi, uint16_t* __restrict__ lo)
{
    int t = blockIdx.x * blockDim.x + threadIdx.x;
    if (t >= B_C * 64) return;
    int b = t >> 6, q = t & 63;
    long long off = (long long)ids[b] * MEM_C + q * 4;
    uint2 h, l;
    split4(*(const float4*)(mem + off), h, l);
    *(uint2*)(hi + off) = h;
    *(uint2*)(lo + off) = l;
}

// ---------------------------------------------------------------------------
// Unified mma.sync bf16-split GEMM engine, cp.async double-buffered.
// MODE 0: C[gb][quarters] = D + bias      (IC / ID precompute)
// MODE 1: regular step (slices 1,3), in-place fp32 mem update (NO bf16 write)
// MODE 2: final step fully fused (all 4 slices), in-place update
// ---------------------------------------------------------------------------
template<int MODE>
__global__ __launch_bounds__(256, 2)
void mma_gemm(const uint16_t* __restrict__ Ahi, const uint16_t* __restrict__ Alo,
              const int* __restrict__ ids, int M,
              const uint16_t* __restrict__ Whi, const uint16_t* __restrict__ Wlo,
              const float* __restrict__ bias,
              const float* __restrict__ X, const float* __restrict__ Y,
              float* __restrict__ C, float* __restrict__ memv)
{
    extern __shared__ __align__(16) char smem[];
    const int tid = threadIdx.x, lane = tid & 31, wid = tid >> 5;
    const int g = blockIdx.x, row0 = blockIdx.y * 128;

    int r0q, r1q, r2q, r3q;
    if (MODE == 0)      { r0q = 64*g;     r1q = r0q + 32; r2q = 256 + 64*g; r3q = r2q + 32; }
    else if (MODE == 1) { r0q = 256+64*g; r1q = r0q + 32; r2q = 768 + 64*g; r3q = r2q + 32; }
    else                { r0q = 32*g;     r1q = 256+32*g; r2q = 512 + 32*g; r3q = 768 + 32*g; }

    int* srow = (int*)(smem + SM_SROW);
    if (tid < 128) {
        int gr = row0 + tid;
        if (gr >= M) gr = M - 1;
        srow[tid] = ids ? ids[gr] : gr;
    }
    __syncthreads();

    // cp.async loader mapping
    const int quad = tid & 3;
    const int rA0 = tid >> 2;          // rows 0..63
    const int rA1 = 64 + (tid >> 2);   // rows 64..127
    const uint32_t sb = smem_u32(smem);

    auto wrow_of = [&](int r) {
        int q = r >> 5;
        int base = (q == 0 ? r0q : q == 1 ? r1q : q == 2 ? r2q : r3q);
        return base + (r & 31);
    };
    const uint16_t* a0h = Ahi + (long long)srow[rA0] * MEM_C + quad * 8;
    const uint16_t* a0l = Alo + (long long)srow[rA0] * MEM_C + quad * 8;
    const uint16_t* a1h = Ahi + (long long)srow[rA1] * MEM_C + quad * 8;
    const uint16_t* a1l = Alo + (long long)srow[rA1] * MEM_C + quad * 8;
    const uint16_t* b0h = Whi + (long long)wrow_of(rA0) * MEM_C + quad * 8;
    const uint16_t* b0l = Wlo + (long long)wrow_of(rA0) * MEM_C + quad * 8;
    const uint16_t* b1h = Whi + (long long)wrow_of(rA1) * MEM_C + quad * 8;
    const uint16_t* b1l = Wlo + (long long)wrow_of(rA1) * MEM_C + quad * 8;
    const uint32_t dA0 = sb + ST_A_HI + rA0 * 80 + quad * 16;
    const uint32_t dA1 = sb + ST_A_HI + rA1 * 80 + quad * 16;
    const uint32_t dB0 = sb + ST_B_HI + rA0 * 80 + quad * 16;
    const uint32_t dB1 = sb + ST_B_HI + rA1 * 80 + quad * 16;

    // ldmatrix lane bases
    const int wm = wid >> 2, wn = wid & 3;
    const uint32_t aoff = sb + ST_A_HI +
        (64*wm + (lane & 7) + 8*((lane >> 3) & 1)) * 80 + (lane >> 4) * 16;
    const uint32_t boff0 = sb + ST_B_HI +
        (32*wn + (lane & 7) + (lane >> 4) * 8) * 80 + ((lane >> 3) & 1) * 16;
    const uint32_t boff1 = boff0 + 16 * 80;

    float acc[4][4][4];
#pragma unroll
    for (int i = 0; i < 4; ++i)
#pragma unroll
        for (int j = 0; j < 4; ++j)
#pragma unroll
            for (int e = 0; e < 4; ++e) acc[i][j][e] = 0.0f;

    auto issue = [&](int kb, uint32_t so) {
        CP16(dA0 + so,             a0h + kb);
        CP16(dA0 + so + 10240,     a0l + kb);
        CP16(dA1 + so,             a1h + kb);
        CP16(dA1 + so + 10240,     a1l + kb);
        CP16(dB0 + so,             b0h + kb);
        CP16(dB0 + so + 10240,     b0l + kb);
        CP16(dB1 + so,             b1h + kb);
        CP16(dB1 + so + 10240,     b1l + kb);
    };

    issue(0, 0);
    CP_COMMIT();

#pragma unroll 1
    for (int kc = 0; kc < 8; ++kc) {
        const uint32_t so = (uint32_t)(kc & 1) * ST_SIZE;
        if (kc < 7) {
            issue((kc + 1) * 32, (uint32_t)((kc + 1) & 1) * ST_SIZE);
            CP_COMMIT();
            CP_WAIT1();
        } else {
            CP_WAIT0();
        }
        __syncthreads();
#pragma unroll
        for (int kk = 0; kk < 2; ++kk) {
            uint32_t ka  = aoff  + so + kk * 32;
            uint32_t kb0 = boff0 + so + kk * 32;
            uint32_t kb1 = boff1 + so + kk * 32;
            uint32_t ah[4][4], al[4][4], bh[4][2], bl[4][2];
#pragma unroll
            for (int tm = 0; tm < 4; ++tm) {
                LDM4(ah[tm][0], ah[tm][1], ah[tm][2], ah[tm][3], ka + tm * 1280);
                LDM4(al[tm][0], al[tm][1], al[tm][2], al[tm][3], ka + tm * 1280 + 10240);
            }
            LDM4(bh[0][0], bh[0][1], bh[1][0], bh[1][1], kb0);
            LDM4(bh[2][0], bh[2][1], bh[3][0], bh[3][1], kb1);
            LDM4(bl[0][0], bl[0][1], bl[1][0], bl[1][1], kb0 + 10240);
            LDM4(bl[2][0], bl[2][1], bl[3][0], bl[3][1], kb1 + 10240);
            // Per-acc add order hh, hl, lh (numerics fixed); scheduler free.
#pragma unroll
            for (int tm = 0; tm < 4; ++tm)
#pragma unroll
                for (int tn = 0; tn < 4; ++tn)
                    MMA_BF16(acc[tm][tn], ah[tm], bh[tn]);
#pragma unroll
            for (int tm = 0; tm < 4; ++tm)
#pragma unroll
                for (int tn = 0; tn < 4; ++tn)
                    MMA_BF16(acc[tm][tn], ah[tm], bl[tn]);
#pragma unroll
            for (int tm = 0; tm < 4; ++tm)
#pragma unroll
                for (int tn = 0; tn < 4; ++tn)
                    MMA_BF16(acc[tm][tn], al[tm], bh[tn]);
        }
        __syncthreads();   // WAR: next issue() targets the buffer just read
    }

    // Stage D through smem, 132-float row stride
    float* Cs = (float*)smem;
#pragma unroll
    for (int tm = 0; tm < 4; ++tm)
#pragma unroll
        for (int tn = 0; tn < 4; ++tn) {
            int rr = 64*wm + 16*tm + (lane >> 2);
            int cc = 32*wn + 8*tn + 2*(lane & 3);
            Cs[rr * 132 + cc]       = acc[tm][tn][0];
            Cs[rr * 132 + cc + 1]   = acc[tm][tn][1];
            Cs[(rr+8) * 132 + cc]     = acc[tm][tn][2];
            Cs[(rr+8) * 132 + cc + 1] = acc[tm][tn][3];
        }
    __syncthreads();

    const int r = tid >> 1, seg = tid & 1;
    const int gb = row0 + r;
    if (gb < M) {
        if (MODE == 0) {
#pragma unroll
            for (int qq = 0; qq < 2; ++qq) {
                int qi = 2*seg + qq;
                int ob = (qi == 0 ? r0q : qi == 1 ? r1q : qi == 2 ? r2q : r3q);
#pragma unroll
                for (int jj = 0; jj < 32; jj += 4) {
                    float4 v  = *(float4*)&Cs[r * 132 + qi * 32 + jj];
                    float4 bv = *(const float4*)(bias + ob + jj);
                    v.x += bv.x; v.y += bv.y; v.z += bv.z; v.w += bv.w;
                    *(float4*)(C + (long long)gb * 512 + ob + jj) = v;
                }
            }
        } else if (MODE == 1) {
            int nid = srow[r];
            int c0 = r0q - 256;  // 64g
#pragma unroll
            for (int jj = 32*seg; jj < 32*seg + 32; jj += 4) {
                float4 hg4 = *(float4*)&Cs[r * 132 + jj];
                float4 ht4 = *(float4*)&Cs[r * 132 + 64 + jj];
                float4 bg = *(const float4*)(bias + r0q + jj);
                float4 bt = *(const float4*)(bias + r2q + jj);
                float4 xg = *(const float4*)(X + (long long)gb * 512 + c0 + jj);
                float4 xt = *(const float4*)(X + (long long)gb * 512 + r0q + jj);
                float4 mg = *(const float4*)(memv + (long long)nid * 256 + c0 + jj);
                float o[4];
                const float* HG = (const float*)&hg4; const float* HT = (const float*)&ht4;
                const float* BG = (const float*)&bg;  const float* BT = (const float*)&bt;
                const float* XG = (const float*)&xg;  const float* XT = (const float*)&xt;
                const float* MG = (const float*)&mg;
#pragma unroll
                for (int e = 0; e < 4; ++e) {
                    float gg = 1.0f / (1.0f + __expf(-(XG[e] + HG[e] + BG[e])));
                    float tt = tanhf(XT[e] + HT[e] + BT[e]);
                    o[e] = (1.0f - gg) * tt + gg * MG[e];
                }
                *(float4*)(memv + (long long)nid * 256 + c0 + jj) =
                    make_float4(o[0], o[1], o[2], o[3]);
            }
        } else {
            int nid = srow[r];
            int c0 = r0q;  // 32g
#pragma unroll
            for (int jj = 16*seg; jj < 16*seg + 16; jj += 4) {
                float4 hgd = *(float4*)&Cs[r * 132 + jj];
                float4 hgc = *(float4*)&Cs[r * 132 + 32 + jj];
                float4 hhd = *(float4*)&Cs[r * 132 + 64 + jj];
                float4 hhc = *(float4*)&Cs[r * 132 + 96 + jj];
                float4 b0 = *(const float4*)(bias + r0q + jj);
                float4 b1 = *(const float4*)(bias + r1q + jj);
                float4 b2 = *(const float4*)(bias + r2q + jj);
                float4 b3 = *(const float4*)(bias + r3q + jj);
                float4 icg = *(const float4*)(X + (long long)gb * 512 + r0q + jj);
                float4 ich = *(const float4*)(X + (long long)gb * 512 + r1q + jj);
                float4 idg = *(const float4*)(Y + (long long)gb * 512 + r0q + jj);
                float4 idh = *(const float4*)(Y + (long long)gb * 512 + r1q + jj);
                float4 mg = *(const float4*)(memv + (long long)nid * 256 + c0 + jj);
                float o[4];
                const float* P0 = (const float*)&hgd; const float* P1 = (const float*)&hgc;
                const float* P2 = (const float*)&hhd; const float* P3 = (const float*)&hhc;
                const float* B0 = (const float*)&b0;  const float* B1 = (const float*)&b1;
                const float* B2 = (const float*)&b2;  const float* B3 = (const float*)&b3;
                const float* ICG = (const float*)&icg; const float* ICH = (const float*)&ich;
                const float* IDG = (const float*)&idg; const float* IDH = (const float*)&idh;
                const float* MG = (const float*)&mg;
#pragma unroll
                for (int e = 0; e < 4; ++e) {
                    float GD = 1.0f / (1.0f + __expf(-(IDG[e] + P0[e] + B0[e])));
                    float GC = 1.0f / (1.0f + __expf(-(ICG[e] + P1[e] + B1[e])));
                    float hD = tanhf(IDH[e] + P2[e] + B2[e]);
                    float hC = tanhf(ICH[e] + P3[e] + B3[e]);
                    o[e] = 0.5f * (GD * hD + GC * hC + (2.0f - GD - GC) * MG[e]);
                }
                *(float4*)(memv + (long long)nid * 256 + c0 + jj) =
                    make_float4(o[0], o[1], o[2], o[3]);
            }
        }
    }
}

// ---------------------------------------------------------------------------
extern "C" void kernel_launch(void* const* d_in, const int* in_sizes, int n_in,
                              void* d_out, int out_size)
{
    const float* memory   = (const float*)d_in[0];
    const void*  node_raw = d_in[1];
    const float* messages = (const float*)d_in[2];
    const float* dtdg     = (const float*)d_in[3];
    const float* WCw      = (const float*)d_in[4];
    const float* WCb      = (const float*)d_in[5];
    const float* WDw      = (const float*)d_in[6];
    const float* WDb      = (const float*)d_in[7];
    const float* Whw      = (const float*)d_in[8];
    const float* Whb      = (const float*)d_in[9];
    float* mem = (float*)d_out;

    float *IC, *IDb; int *IDS;
    uint16_t *MSGhi, *MSGlo, *MEMhi, *MEMlo, *DThi, *DTlo;
    uint16_t *WChi, *WClo, *WDhi, *WDlo, *Whhi, *Whlo;
    cudaGetSymbolAddress((void**)&IC,    g_IC);
    cudaGetSymbolAddress((void**)&IDb,   g_ID);
    cudaGetSymbolAddress((void**)&IDS,   g_IDS);
    cudaGetSymbolAddress((void**)&MSGhi, g_MSGhi);
    cudaGetSymbolAddress((void**)&MSGlo, g_MSGlo);
    cudaGetSymbolAddress((void**)&MEMhi, g_MEMhi);
    cudaGetSymbolAddress((void**)&MEMlo, g_MEMlo);
    cudaGetSymbolAddress((void**)&DThi,  g_DThi);
    cudaGetSymbolAddress((void**)&DTlo,  g_DTlo);
    cudaGetSymbolAddress((void**)&WChi,  g_WChi);
    cudaGetSymbolAddress((void**)&WClo,  g_WClo);
    cudaGetSymbolAddress((void**)&WDhi,  g_WDhi);
    cudaGetSymbolAddress((void**)&WDlo,  g_WDlo);
    cudaGetSymbolAddress((void**)&Whhi,  g_Whhi);
    cudaGetSymbolAddress((void**)&Whlo,  g_Whlo);

    // One-time stream/event setup (host-side resources only; the captured
    // graph is identical on every call).
    static cudaStream_t s2 = nullptr;
    static cudaEvent_t evFork, evID, evIC[DIV_C];
    if (!s2) {
        cudaStreamCreateWithFlags(&s2, cudaStreamNonBlocking);
        cudaEventCreateWithFlags(&evFork, cudaEventDisableTiming);
        cudaEventCreateWithFlags(&evID,   cudaEventDisableTiming);
        for (int i = 0; i < DIV_C; ++i)
            cudaEventCreateWithFlags(&evIC[i], cudaEventDisableTiming);
    }

    cudaFuncSetAttribute(mma_gemm<0>, cudaFuncAttributeMaxDynamicSharedMemorySize, SM_TOTAL);
    cudaFuncSetAttribute(mma_gemm<1>, cudaFuncAttributeMaxDynamicSharedMemorySize, SM_TOTAL);
    cudaFuncSetAttribute(mma_gemm<2>, cudaFuncAttributeMaxDynamicSharedMemorySize, SM_TOTAL);

    // --- Main stream: prep work ---
    cudaMemcpyAsync(mem, memory, (size_t)N_NODES_C * MEM_C * sizeof(float),
                    cudaMemcpyDeviceToDevice);

    normalize_ids<<<(DIV_C * B_C + 255) / 256, 256>>>(
        (const unsigned int*)node_raw, IDS, DIV_C * B_C);

    const long long n4_msg = (long long)DIV_C * B_C * MEM_C / 4;
    const long long n4_mem = (long long)N_NODES_C * MEM_C / 4;
    cvt_split<<<(int)((n4_msg + 255) / 256), 256>>>(messages, MSGhi, MSGlo, n4_msg);
    cvt_split<<<(int)((n4_mem + 255) / 256), 256>>>(memory, MEMhi, MEMlo, n4_mem);
    cvt_split<<<(512 * MEM_C / 4 + 255) / 256, 256>>>(WCw, WChi, WClo, 512 * MEM_C / 4);
    cvt_split<<<(512 * MEM_C / 4 + 255) / 256, 256>>>(WDw, WDhi, WDlo, 512 * MEM_C / 4);
    cvt_split<<<(1024 * MEM_C / 4 + 255) / 256, 256>>>(Whw, Whhi, Whlo, 1024 * MEM_C / 4);

    const int* ids7 = IDS + (DIV_C - 1) * B_C;
    cvt_gather<<<(B_C * 64 + 255) / 256, 256>>>(dtdg, ids7, DThi, DTlo);

    const int gy = (B_C + 127) / 128;  // 157
    const int rfb = (B_C * 64 + 255) / 256;

    // --- Fork: IC parts + ID on side stream, overlapped with the step chain ---
    cudaEventRecord(evFork, 0);
    cudaStreamWaitEvent(s2, evFork, 0);

    for (int s = 0; s < DIV_C; ++s) {
        const long long ao = (long long)s * B_C * MEM_C;
        mma_gemm<0><<<dim3(4, gy), 256, SM_TOTAL, s2>>>(
            MSGhi + ao, MSGlo + ao, nullptr, B_C, WChi, WClo, WCb,
            nullptr, nullptr, IC + (long long)s * B_C * 512, nullptr);
        cudaEventRecord(evIC[s], s2);
    }
    mma_gemm<0><<<dim3(4, gy), 256, SM_TOTAL, s2>>>(
        DThi, DTlo, nullptr, B_C, WDhi, WDlo, WDb,
        nullptr, nullptr, IDb, nullptr);
    cudaEventRecord(evID, s2);

    // --- Main stream: sequential step chain, each gated on its IC slice.
    // Step kernel updates fp32 mem only; refresh_rows then rebuilds the
    // bf16 hi/lo mirror for the updated rows (race-free by kernel boundary).
    for (int s = 0; s < DIV_C - 1; ++s) {
        cudaStreamWaitEvent(0, evIC[s], 0);
        mma_gemm<1><<<dim3(4, gy), 256, SM_TOTAL>>>(
            MEMhi, MEMlo, IDS + s * B_C, B_C, Whhi, Whlo, Whb,
            IC + (long long)s * B_C * 512, nullptr, nullptr, mem);
        refresh_rows<<<rfb, 256>>>(mem, IDS + s * B_C, MEMhi, MEMlo);
    }
    cudaStreamWaitEvent(0, evIC[DIV_C - 1], 0);
    cudaStreamWaitEvent(0, evID, 0);
    mma_gemm<2><<<dim3(8, gy), 256, SM_TOTAL>>>(
        MEMhi, MEMlo, ids7, B_C, Whhi, Whlo, Whb,
        IC + (long long)(DIV_C - 1) * B_C * 512, IDb, nullptr, mem);
}